// round 9
// baseline (speedup 1.0000x reference)
#include <cuda_runtime.h>
#include <cuda_bf16.h>
#include <math.h>
#include <stdint.h>

#define NNODE 100000
#define MAXE  3400000
#define FIN   512
#define HID   256
#define CLS   64

// ---------------- scratch (static device globals; no allocation) ----------------
__device__ float    g_Hm[(size_t)NNODE * HID];   // elu(x@Wm0+bm0)
__device__ float    g_Hv[(size_t)NNODE * HID];   // relu(x@Wv0+bv0)
__device__ uint32_t g_m64b[(size_t)NNODE * 32];  // mean*attn, bf16x2 packed
__device__ uint32_t g_v64b[(size_t)NNODE * 32];  // var*attn^2, bf16x2 packed
__device__ int      g_ecnt[NNODE];               // out-degree (no self loop)
__device__ int      g_rowstart[NNODE];           // CSR row starts
__device__ int      g_fill[NNODE];               // scatter cursors
__device__ int      g_bsums[128];                // scan block sums
__device__ int      g_eidx[MAXE];                // CSR dst indices
__device__ float    g_dis[NNODE];                // deg^-0.5
__device__ float    g_di[NNODE];                 // deg^-1

// ---------------- degree + CSR build ----------------
__global__ void zero_ecnt_kernel(int n) {
    int i = blockIdx.x * blockDim.x + threadIdx.x;
    if (i < n) g_ecnt[i] = 0;
}
__global__ void count_edges_kernel(const int* __restrict__ src, int e) {
    int i = blockIdx.x * blockDim.x + threadIdx.x;
    if (i < e) atomicAdd(&g_ecnt[src[i]], 1);
}
__global__ __launch_bounds__(1024) void scan_blocks_kernel(int n) {
    __shared__ int sh[1024];
    int tid = threadIdx.x;
    int gid = blockIdx.x * 1024 + tid;
    int v = (gid < n) ? g_ecnt[gid] : 0;
    sh[tid] = v;
    __syncthreads();
    for (int off = 1; off < 1024; off <<= 1) {
        int t = (tid >= off) ? sh[tid - off] : 0;
        __syncthreads();
        sh[tid] += t;
        __syncthreads();
    }
    if (gid < n) g_rowstart[gid] = sh[tid] - v;   // exclusive
    if (tid == 1023) g_bsums[blockIdx.x] = sh[1023];
}
__global__ void scan_tops_kernel(int nblk) {
    __shared__ int sh[128];
    int tid = threadIdx.x;
    int v = (tid < nblk) ? g_bsums[tid] : 0;
    sh[tid] = v;
    __syncthreads();
    for (int off = 1; off < 128; off <<= 1) {
        int t = (tid >= off) ? sh[tid - off] : 0;
        __syncthreads();
        sh[tid] += t;
        __syncthreads();
    }
    if (tid < nblk) g_bsums[tid] = sh[tid] - v;   // exclusive
}
// scan finalize + degree weights (fused)
__global__ void scan_add_deg_kernel(int n) {
    int i = blockIdx.x * blockDim.x + threadIdx.x;
    if (i < n) {
        int rs = g_rowstart[i] + g_bsums[i >> 10];
        g_rowstart[i] = rs;
        g_fill[i] = rs;
        float c = (float)(g_ecnt[i] + 1);   // + self loop
        g_dis[i] = 1.0f / sqrtf(c);
        g_di[i]  = 1.0f / c;
    }
}
__global__ void scatter_edges_kernel(const int* __restrict__ src,
                                     const int* __restrict__ dst, int e) {
    int i = blockIdx.x * blockDim.x + threadIdx.x;
    if (i < e) {
        int pos = atomicAdd(&g_fill[src[i]], 1);
        g_eidx[pos] = dst[i];
    }
}

// ---------------- mma.sync + cp.async helpers (legal at compute_103) ------------
__device__ __forceinline__ void mma_tf32(float* c, const uint32_t* a, const uint32_t* b) {
    asm volatile(
        "mma.sync.aligned.m16n8k8.row.col.f32.tf32.tf32.f32 "
        "{%0,%1,%2,%3}, {%4,%5,%6,%7}, {%8,%9}, {%0,%1,%2,%3};"
        : "+f"(c[0]), "+f"(c[1]), "+f"(c[2]), "+f"(c[3])
        : "r"(a[0]), "r"(a[1]), "r"(a[2]), "r"(a[3]), "r"(b[0]), "r"(b[1]));
}
__device__ __forceinline__ uint32_t smem_u32(const void* p) {
    uint32_t a;
    asm("{ .reg .u64 t; cvta.to.shared.u64 t, %1; cvt.u32.u64 %0, t; }" : "=r"(a) : "l"(p));
    return a;
}
__device__ __forceinline__ void cp_async16(uint32_t dst, const void* src, int srcsize) {
    asm volatile("cp.async.cg.shared.global [%0], [%1], 16, %2;"
                 :: "r"(dst), "l"(src), "r"(srcsize) : "memory");
}
__device__ __forceinline__ void cp_commit() {
    asm volatile("cp.async.commit_group;" ::: "memory");
}
__device__ __forceinline__ void cp_wait2() {
    asm volatile("cp.async.wait_group 2;" ::: "memory");
}
__device__ __forceinline__ void cp_wait1() {
    asm volatile("cp.async.wait_group 1;" ::: "memory");
}
__device__ __forceinline__ void cp_wait0() {
    asm volatile("cp.async.wait_group 0;" ::: "memory");
}

// ---------------- layer-0 GEMM: H = act(X @ W + b), cp.async 4-stage -------------
// BM=128, BN=128, BK=16, 256 thr (8 warps 2x4), warp tile 64x32.
#define G0_ASTR 20
#define G0_BSTR 136
#define G0_STAGE (128 * G0_ASTR + 16 * G0_BSTR)   // 4736 floats
#define G0_SMEM  (4 * G0_STAGE * 4)               // 75776 bytes

__global__ __launch_bounds__(256) void gemm0_mma_kernel(
    const float* __restrict__ X,
    const float* __restrict__ Wm, const float* __restrict__ bm,
    const float* __restrict__ Wv, const float* __restrict__ bv,
    int M)
{
    extern __shared__ float smem[];

    int nb   = blockIdx.x & 1;
    int path = blockIdx.x >> 1;
    const float* W    = path ? Wv : Wm;
    const float* bias = path ? bv : bm;
    float* H          = path ? g_Hv : g_Hm;

    int rowBase = blockIdx.y * 128;
    int t = threadIdx.x, wid = t >> 5, lane = t & 31;
    int warpM = wid >> 2, warpN = wid & 3;
    int lr = lane >> 2, lc = lane & 3;

    int mA0 = t >> 2,        kqA = t & 3;
    int mA1 = (t + 256) >> 2;
    int k2B0 = t >> 5,       nqB = t & 31;
    int k2B1 = (t + 256) >> 5;
    int szA0 = (rowBase + mA0 < M) ? 16 : 0;
    int szA1 = (rowBase + mA1 < M) ? 16 : 0;
    const float* XA0 = X + (size_t)(rowBase + mA0) * FIN + kqA * 4;
    const float* XA1 = X + (size_t)(rowBase + mA1) * FIN + kqA * 4;
    const float* WB0 = W + (size_t)k2B0 * HID + nb * 128 + nqB * 4;
    const float* WB1 = W + (size_t)k2B1 * HID + nb * 128 + nqB * 4;
    uint32_t dA0 = smem_u32(&smem[mA0 * G0_ASTR + kqA * 4]);
    uint32_t dA1 = smem_u32(&smem[mA1 * G0_ASTR + kqA * 4]);
    uint32_t dB0 = smem_u32(&smem[128 * G0_ASTR + k2B0 * G0_BSTR + nqB * 4]);
    uint32_t dB1 = smem_u32(&smem[128 * G0_ASTR + k2B1 * G0_BSTR + nqB * 4]);

    float acc[4][4][4];
    #pragma unroll
    for (int i = 0; i < 4; i++)
        #pragma unroll
        for (int j = 0; j < 4; j++)
            #pragma unroll
            for (int q = 0; q < 4; q++) acc[i][j][q] = 0.0f;

    // prologue: stages 0,1,2
    #pragma unroll
    for (int pc = 0; pc < 3; pc++) {
        uint32_t so = pc * G0_STAGE * 4;
        cp_async16(dA0 + so, XA0 + pc * 16, szA0);
        cp_async16(dA1 + so, XA1 + pc * 16, szA1);
        cp_async16(dB0 + so, WB0 + (size_t)pc * 16 * HID, 16);
        cp_async16(dB1 + so, WB1 + (size_t)pc * 16 * HID, 16);
        cp_commit();
    }

    for (int c = 0; c < 32; c++) {
        if (c < 30) cp_wait2(); else if (c == 30) cp_wait1(); else cp_wait0();
        __syncthreads();

        int cur = c & 3;
        const float* sA = smem + cur * G0_STAGE;
        const float* sB = sA + 128 * G0_ASTR;

        #pragma unroll
        for (int ks = 0; ks < 2; ks++) {
            int kb = ks * 8;
            uint32_t afr[4][4];
            #pragma unroll
            for (int mt = 0; mt < 4; mt++) {
                int m0 = warpM * 64 + mt * 16 + lr;
                afr[mt][0] = __float_as_uint(sA[m0 * G0_ASTR + kb + lc]);
                afr[mt][1] = __float_as_uint(sA[(m0 + 8) * G0_ASTR + kb + lc]);
                afr[mt][2] = __float_as_uint(sA[m0 * G0_ASTR + kb + lc + 4]);
                afr[mt][3] = __float_as_uint(sA[(m0 + 8) * G0_ASTR + kb + lc + 4]);
            }
            #pragma unroll
            for (int nt = 0; nt < 4; nt++) {
                int n0 = warpN * 32 + nt * 8 + lr;
                uint32_t bfr[2];
                bfr[0] = __float_as_uint(sB[(kb + lc) * G0_BSTR + n0]);
                bfr[1] = __float_as_uint(sB[(kb + lc + 4) * G0_BSTR + n0]);
                #pragma unroll
                for (int mt = 0; mt < 4; mt++) mma_tf32(acc[mt][nt], afr[mt], bfr);
            }
        }

        if (c + 3 < 32) {
            int cn = c + 3;
            uint32_t so = (cn & 3) * G0_STAGE * 4;
            cp_async16(dA0 + so, XA0 + cn * 16, szA0);
            cp_async16(dA1 + so, XA1 + cn * 16, szA1);
            cp_async16(dB0 + so, WB0 + (size_t)cn * 16 * HID, 16);
            cp_async16(dB1 + so, WB1 + (size_t)cn * 16 * HID, 16);
            cp_commit();
        }
    }

    // epilogue: bias + activation, fp32 store
    #pragma unroll
    for (int mt = 0; mt < 4; mt++) {
        int r0 = rowBase + warpM * 64 + mt * 16 + lr;
        #pragma unroll
        for (int nt = 0; nt < 4; nt++) {
            int cb = nb * 128 + warpN * 32 + nt * 8 + lc * 2;
            float b0 = bias[cb], b1 = bias[cb + 1];
            #pragma unroll
            for (int half = 0; half < 2; half++) {
                int r = r0 + half * 8;
                if (r >= M) continue;
                float v0 = acc[mt][nt][half * 2 + 0] + b0;
                float v1 = acc[mt][nt][half * 2 + 1] + b1;
                if (path == 0) {
                    v0 = (v0 > 0.0f) ? v0 : expm1f(v0);
                    v1 = (v1 > 0.0f) ? v1 : expm1f(v1);
                } else {
                    v0 = fmaxf(v0, 0.0f);
                    v1 = fmaxf(v1, 0.0f);
                }
                *(float2*)(H + (size_t)r * HID + cb) = make_float2(v0, v1);
            }
        }
    }
}

// ---------------- layer-1 via tf32 HMMA, cp.async 3-stage ------------------------
// BM=128, BN=64, K=256 per path; both paths sequential; attn-coupled epilogue
// writing bf16x2-packed m64b/v64b.
#define L1_ASTR 20
#define L1_BSTR 72
#define L1_STAGE (128 * L1_ASTR + 16 * L1_BSTR)   // 3712 floats
#define L1_SMEM  (3 * L1_STAGE * 4)               // 44544 bytes

__global__ __launch_bounds__(256) void layer1_mma_kernel(
    const float* __restrict__ Wm1, const float* __restrict__ bm1,
    const float* __restrict__ Wv1, const float* __restrict__ bv1,
    int M)
{
    extern __shared__ float smem[];

    int rowBase = blockIdx.x * 128;
    int t = threadIdx.x, wid = t >> 5, lane = t & 31;
    int warpM = wid >> 2, warpN = wid & 3;
    int lr = lane >> 2, lc = lane & 3;

    int mA0 = t >> 2,        kqA = t & 3;
    int mA1 = (t + 256) >> 2;
    int k2B = t >> 4,        nqB = t & 15;
    int szA0 = (rowBase + mA0 < M) ? 16 : 0;
    int szA1 = (rowBase + mA1 < M) ? 16 : 0;
    uint32_t dA0 = smem_u32(&smem[mA0 * L1_ASTR + kqA * 4]);
    uint32_t dA1 = smem_u32(&smem[mA1 * L1_ASTR + kqA * 4]);
    uint32_t dB  = smem_u32(&smem[128 * L1_ASTR + k2B * L1_BSTR + nqB * 4]);

    float acc0[4][2][4], acc1[4][2][4];
    #pragma unroll
    for (int i = 0; i < 4; i++)
        #pragma unroll
        for (int j = 0; j < 2; j++)
            #pragma unroll
            for (int q = 0; q < 4; q++) { acc0[i][j][q] = 0.f; acc1[i][j][q] = 0.f; }

    #pragma unroll
    for (int p = 0; p < 2; p++) {
        const float* A = p ? g_Hv : g_Hm;
        const float* W = p ? Wv1 : Wm1;
        const float* A0 = A + (size_t)(rowBase + mA0) * HID + kqA * 4;
        const float* A1 = A + (size_t)(rowBase + mA1) * HID + kqA * 4;
        const float* WB = W + (size_t)k2B * CLS + nqB * 4;

        __syncthreads();   // previous path's consumers done before overwrite

        #pragma unroll
        for (int pc = 0; pc < 2; pc++) {
            uint32_t so = pc * L1_STAGE * 4;
            cp_async16(dA0 + so, A0 + pc * 16, szA0);
            cp_async16(dA1 + so, A1 + pc * 16, szA1);
            cp_async16(dB + so, WB + (size_t)pc * 16 * CLS, 16);
            cp_commit();
        }

        for (int c = 0; c < 16; c++) {
            if (c < 14) cp_wait1(); else cp_wait0();
            __syncthreads();

            int cur = c - (c / 3) * 3;
            const float* sA = smem + cur * L1_STAGE;
            const float* sB = sA + 128 * L1_ASTR;

            #pragma unroll
            for (int ks = 0; ks < 2; ks++) {
                int kb = ks * 8;
                uint32_t afr[4][4];
                #pragma unroll
                for (int mt = 0; mt < 4; mt++) {
                    int m0 = warpM * 64 + mt * 16 + lr;
                    afr[mt][0] = __float_as_uint(sA[m0 * L1_ASTR + kb + lc]);
                    afr[mt][1] = __float_as_uint(sA[(m0 + 8) * L1_ASTR + kb + lc]);
                    afr[mt][2] = __float_as_uint(sA[m0 * L1_ASTR + kb + lc + 4]);
                    afr[mt][3] = __float_as_uint(sA[(m0 + 8) * L1_ASTR + kb + lc + 4]);
                }
                #pragma unroll
                for (int nt = 0; nt < 2; nt++) {
                    int n0 = warpN * 16 + nt * 8 + lr;
                    uint32_t bfr[2];
                    bfr[0] = __float_as_uint(sB[(kb + lc) * L1_BSTR + n0]);
                    bfr[1] = __float_as_uint(sB[(kb + lc + 4) * L1_BSTR + n0]);
                    #pragma unroll
                    for (int mt = 0; mt < 4; mt++)
                        mma_tf32(p ? acc1[mt][nt] : acc0[mt][nt], afr[mt], bfr);
                }
            }

            if (c + 2 < 16) {
                int cn = c + 2;
                int s  = cn - (cn / 3) * 3;
                uint32_t so = s * L1_STAGE * 4;
                cp_async16(dA0 + so, A0 + cn * 16, szA0);
                cp_async16(dA1 + so, A1 + cn * 16, szA1);
                cp_async16(dB + so, WB + (size_t)cn * 16 * CLS, 16);
                cp_commit();
            }
        }
    }

    // fused epilogue: elu/relu + attn coupling, write bf16x2-packed m64b/v64b
    #pragma unroll
    for (int mt = 0; mt < 4; mt++) {
        int r0 = rowBase + warpM * 64 + mt * 16 + lr;
        #pragma unroll
        for (int nt = 0; nt < 2; nt++) {
            int cb = warpN * 16 + nt * 8 + lc * 2;
            float bm0c = bm1[cb], bm1c = bm1[cb + 1];
            float bv0c = bv1[cb], bv1c = bv1[cb + 1];
            #pragma unroll
            for (int half = 0; half < 2; half++) {
                int r = r0 + half * 8;
                if (r >= M) continue;
                float m0 = acc0[mt][nt][half * 2 + 0] + bm0c;
                float m1 = acc0[mt][nt][half * 2 + 1] + bm1c;
                m0 = (m0 > 0.0f) ? m0 : expm1f(m0);
                m1 = (m1 > 0.0f) ? m1 : expm1f(m1);
                float v0 = fmaxf(acc1[mt][nt][half * 2 + 0] + bv0c, 0.0f) + 1e-6f;
                float v1 = fmaxf(acc1[mt][nt][half * 2 + 1] + bv1c, 0.0f) + 1e-6f;
                float a0 = expf(-v0), a1 = expf(-v1);
                __nv_bfloat162 pm = __float22bfloat162_rn(make_float2(m0 * a0, m1 * a1));
                __nv_bfloat162 pv = __float22bfloat162_rn(make_float2(v0 * a0 * a0, v1 * a1 * a1));
                size_t o = (size_t)r * 32 + (cb >> 1);
                g_m64b[o] = *(uint32_t*)&pm;
                g_v64b[o] = *(uint32_t*)&pv;
            }
        }
    }
}

// ---------------- fused SpMM (CSR, bf16 gather, no atomics) + finalize -----------
// warp per node; lane holds cols (2*lane, 2*lane+1).
__global__ __launch_bounds__(256) void spmm_fused_kernel(
    const float* __restrict__ sample, float* __restrict__ out, int n)
{
    int s    = (blockIdx.x * 256 + threadIdx.x) >> 5;
    int lane = threadIdx.x & 31;
    if (s >= n) return;

    float dis_s = g_dis[s], di_s = g_di[s];
    int start = g_rowstart[s];
    int cnt   = g_ecnt[s];

    // self-loop contribution
    float2 msl = __bfloat1622float2(*(__nv_bfloat162*)&g_m64b[(size_t)s * 32 + lane]);
    float2 vsl = __bfloat1622float2(*(__nv_bfloat162*)&g_v64b[(size_t)s * 32 + lane]);
    float am0 = dis_s * dis_s * msl.x;
    float am1 = dis_s * dis_s * msl.y;
    float av0 = di_s * di_s * vsl.x;
    float av1 = di_s * di_s * vsl.y;

    int j = 0;
    for (; j + 4 <= cnt; j += 4) {
        int d0 = g_eidx[start + j];
        int d1 = g_eidx[start + j + 1];
        int d2 = g_eidx[start + j + 2];
        int d3 = g_eidx[start + j + 3];
        float wm0 = dis_s * g_dis[d0], wv0 = di_s * g_di[d0];
        float wm1 = dis_s * g_dis[d1], wv1 = di_s * g_di[d1];
        float wm2 = dis_s * g_dis[d2], wv2 = di_s * g_di[d2];
        float wm3 = dis_s * g_dis[d3], wv3 = di_s * g_di[d3];
        uint32_t mu0 = g_m64b[(size_t)d0 * 32 + lane];
        uint32_t mu1 = g_m64b[(size_t)d1 * 32 + lane];
        uint32_t mu2 = g_m64b[(size_t)d2 * 32 + lane];
        uint32_t mu3 = g_m64b[(size_t)d3 * 32 + lane];
        uint32_t vu0 = g_v64b[(size_t)d0 * 32 + lane];
        uint32_t vu1 = g_v64b[(size_t)d1 * 32 + lane];
        uint32_t vu2 = g_v64b[(size_t)d2 * 32 + lane];
        uint32_t vu3 = g_v64b[(size_t)d3 * 32 + lane];
        float2 m0 = __bfloat1622float2(*(__nv_bfloat162*)&mu0);
        float2 m1 = __bfloat1622float2(*(__nv_bfloat162*)&mu1);
        float2 m2 = __bfloat1622float2(*(__nv_bfloat162*)&mu2);
        float2 m3 = __bfloat1622float2(*(__nv_bfloat162*)&mu3);
        float2 v0 = __bfloat1622float2(*(__nv_bfloat162*)&vu0);
        float2 v1 = __bfloat1622float2(*(__nv_bfloat162*)&vu1);
        float2 v2 = __bfloat1622float2(*(__nv_bfloat162*)&vu2);
        float2 v3 = __bfloat1622float2(*(__nv_bfloat162*)&vu3);
        am0 += wm0 * m0.x + wm1 * m1.x + wm2 * m2.x + wm3 * m3.x;
        am1 += wm0 * m0.y + wm1 * m1.y + wm2 * m2.y + wm3 * m3.y;
        av0 += wv0 * v0.x + wv1 * v1.x + wv2 * v2.x + wv3 * v3.x;
        av1 += wv0 * v0.y + wv1 * v1.y + wv2 * v2.y + wv3 * v3.y;
    }
    for (; j < cnt; j++) {
        int d = g_eidx[start + j];
        float wm = dis_s * g_dis[d], wv = di_s * g_di[d];
        uint32_t mu = g_m64b[(size_t)d * 32 + lane];
        uint32_t vu = g_v64b[(size_t)d * 32 + lane];
        float2 mm = __bfloat1622float2(*(__nv_bfloat162*)&mu);
        float2 vv = __bfloat1622float2(*(__nv_bfloat162*)&vu);
        am0 += wm * mm.x;
        am1 += wm * mm.y;
        av0 += wv * vv.x;
        av1 += wv * vv.y;
    }

    // finalize: out = m + sample*sqrt(v); log_softmax over 64 (lane pair layout)
    size_t base = (size_t)s * CLS;
    float2 sp = *(const float2*)(sample + base + lane * 2);
    float va = am0 + sp.x * sqrtf(fmaxf(av0, 0.f));
    float vb = am1 + sp.y * sqrtf(fmaxf(av1, 0.f));
    float mx = fmaxf(va, vb);
    #pragma unroll
    for (int o = 16; o; o >>= 1) mx = fmaxf(mx, __shfl_xor_sync(0xFFFFFFFFu, mx, o));
    float sum = expf(va - mx) + expf(vb - mx);
    #pragma unroll
    for (int o = 16; o; o >>= 1) sum += __shfl_xor_sync(0xFFFFFFFFu, sum, o);
    float lse = mx + logf(sum);
    *(float2*)(out + base + lane * 2) = make_float2(va - lse, vb - lse);
}

// ---------------- launch ----------------
extern "C" void kernel_launch(void* const* d_in, const int* in_sizes, int n_in,
                              void* d_out, int out_size)
{
    const float* x      = (const float*)d_in[0];
    const float* Wm0    = (const float*)d_in[1];
    const float* bm0    = (const float*)d_in[2];
    const float* Wv0    = (const float*)d_in[3];
    const float* bv0    = (const float*)d_in[4];
    const float* Wm1    = (const float*)d_in[5];
    const float* bm1    = (const float*)d_in[6];
    const float* Wv1    = (const float*)d_in[7];
    const float* bv1    = (const float*)d_in[8];
    const float* sample = (const float*)d_in[9];
    const int*   esrc   = (const int*)d_in[10];
    const int*   edst   = (const int*)d_in[11];
    float* out = (float*)d_out;

    int M = in_sizes[0] / FIN;     // 100000
    int E = in_sizes[10];          // 3200000
    if (M > NNODE) M = NNODE;
    if (E > MAXE)  E = MAXE;
    int nblk = (M + 1023) / 1024;

    cudaFuncSetAttribute(gemm0_mma_kernel, cudaFuncAttributeMaxDynamicSharedMemorySize, G0_SMEM);
    cudaFuncSetAttribute(layer1_mma_kernel, cudaFuncAttributeMaxDynamicSharedMemorySize, L1_SMEM);

    // degree + CSR build
    zero_ecnt_kernel    <<<(M + 255) / 256, 256>>>(M);
    count_edges_kernel  <<<(E + 255) / 256, 256>>>(esrc, E);
    scan_blocks_kernel  <<<nblk, 1024>>>(M);
    scan_tops_kernel    <<<1, 128>>>(nblk);
    scan_add_deg_kernel <<<(M + 255) / 256, 256>>>(M);
    scatter_edges_kernel<<<(E + 255) / 256, 256>>>(esrc, edst, E);

    // dense pipeline
    dim3 g0(4, (M + 127) / 128);
    gemm0_mma_kernel<<<g0, 256, G0_SMEM>>>(x, Wm0, bm0, Wv0, bv0, M);
    layer1_mma_kernel<<<(M + 127) / 128, 256, L1_SMEM>>>(Wm1, bm1, Wv1, bv1, M);

    // graph aggregation + output
    spmm_fused_kernel<<<((size_t)M * 32 + 255) / 256, 256>>>(sample, out, M);
}

// round 11
// speedup vs baseline: 1.4868x; 1.4868x over previous
#include <cuda_runtime.h>
#include <cuda_bf16.h>
#include <math.h>
#include <stdint.h>

#define NNODE 100000
#define MAXE  3400000
#define FIN   512
#define HID   256
#define CLS   64

// ---------------- scratch (static device globals; no allocation) ----------------
__device__ float    g_Hm[(size_t)NNODE * HID];   // elu(x@Wm0+bm0)
__device__ float    g_Hv[(size_t)NNODE * HID];   // relu(x@Wv0+bv0)
__device__ uint32_t g_m64b[(size_t)NNODE * 32];  // mean*attn, bf16x2 packed
__device__ uint32_t g_v64b[(size_t)NNODE * 32];  // var*attn^2, bf16x2 packed
__device__ int      g_ecnt[NNODE];               // out-degree (no self loop)
__device__ int      g_rowstart[NNODE];           // CSR row starts
__device__ int      g_fill[NNODE];               // scatter cursors
__device__ int      g_bsums[128];                // scan block sums
__device__ int      g_eidx[MAXE];                // CSR dst indices
__device__ float    g_dis[NNODE];                // deg^-0.5
__device__ float    g_di[NNODE];                 // deg^-1

// ---------------- degree + CSR build ----------------
__global__ void zero_ecnt_kernel(int n) {
    int i = blockIdx.x * blockDim.x + threadIdx.x;
    if (i < n) g_ecnt[i] = 0;
}
__global__ void count_edges_kernel(const int* __restrict__ src, int e) {
    int i = blockIdx.x * blockDim.x + threadIdx.x;
    if (i < e) atomicAdd(&g_ecnt[src[i]], 1);
}
__global__ __launch_bounds__(1024) void scan_blocks_kernel(int n) {
    __shared__ int sh[1024];
    int tid = threadIdx.x;
    int gid = blockIdx.x * 1024 + tid;
    int v = (gid < n) ? g_ecnt[gid] : 0;
    sh[tid] = v;
    __syncthreads();
    for (int off = 1; off < 1024; off <<= 1) {
        int t = (tid >= off) ? sh[tid - off] : 0;
        __syncthreads();
        sh[tid] += t;
        __syncthreads();
    }
    if (gid < n) g_rowstart[gid] = sh[tid] - v;   // exclusive
    if (tid == 1023) g_bsums[blockIdx.x] = sh[1023];
}
__global__ void scan_tops_kernel(int nblk) {
    __shared__ int sh[128];
    int tid = threadIdx.x;
    int v = (tid < nblk) ? g_bsums[tid] : 0;
    sh[tid] = v;
    __syncthreads();
    for (int off = 1; off < 128; off <<= 1) {
        int t = (tid >= off) ? sh[tid - off] : 0;
        __syncthreads();
        sh[tid] += t;
        __syncthreads();
    }
    if (tid < nblk) g_bsums[tid] = sh[tid] - v;   // exclusive
}
// scan finalize + degree weights (fused)
__global__ void scan_add_deg_kernel(int n) {
    int i = blockIdx.x * blockDim.x + threadIdx.x;
    if (i < n) {
        int rs = g_rowstart[i] + g_bsums[i >> 10];
        g_rowstart[i] = rs;
        g_fill[i] = rs;
        float c = (float)(g_ecnt[i] + 1);   // + self loop
        g_dis[i] = 1.0f / sqrtf(c);
        g_di[i]  = 1.0f / c;
    }
}
__global__ void scatter_edges_kernel(const int* __restrict__ src,
                                     const int* __restrict__ dst, int e) {
    int i = blockIdx.x * blockDim.x + threadIdx.x;
    if (i < e) {
        int pos = atomicAdd(&g_fill[src[i]], 1);
        g_eidx[pos] = dst[i];
    }
}

// ---------------- mma.sync + cp.async helpers (legal at compute_103) ------------
__device__ __forceinline__ void mma_tf32(float* c, const uint32_t* a, const uint32_t* b) {
    asm volatile(
        "mma.sync.aligned.m16n8k8.row.col.f32.tf32.tf32.f32 "
        "{%0,%1,%2,%3}, {%4,%5,%6,%7}, {%8,%9}, {%0,%1,%2,%3};"
        : "+f"(c[0]), "+f"(c[1]), "+f"(c[2]), "+f"(c[3])
        : "r"(a[0]), "r"(a[1]), "r"(a[2]), "r"(a[3]), "r"(b[0]), "r"(b[1]));
}
__device__ __forceinline__ uint32_t smem_u32(const void* p) {
    uint32_t a;
    asm("{ .reg .u64 t; cvta.to.shared.u64 t, %1; cvt.u32.u64 %0, t; }" : "=r"(a) : "l"(p));
    return a;
}
__device__ __forceinline__ void cp_async16(uint32_t dst, const void* src, int srcsize) {
    asm volatile("cp.async.cg.shared.global [%0], [%1], 16, %2;"
                 :: "r"(dst), "l"(src), "r"(srcsize) : "memory");
}
__device__ __forceinline__ void cp_commit() {
    asm volatile("cp.async.commit_group;" ::: "memory");
}
__device__ __forceinline__ void cp_wait1() {
    asm volatile("cp.async.wait_group 1;" ::: "memory");
}
__device__ __forceinline__ void cp_wait0() {
    asm volatile("cp.async.wait_group 0;" ::: "memory");
}

// ---------------- layer-0 GEMM: H = act(X @ W + b), cp.async 3-stage -------------
// BM=128, BN=128, BK=16, 256 thr (8 warps 2x4), warp tile 64x32.  (R7-proven)
#define G0_ASTR 20
#define G0_BSTR 136
#define G0_STAGE (128 * G0_ASTR + 16 * G0_BSTR)   // 4736 floats
#define G0_SMEM  (3 * G0_STAGE * 4)               // 56832 bytes

__global__ __launch_bounds__(256, 2) void gemm0_mma_kernel(
    const float* __restrict__ X,
    const float* __restrict__ Wm, const float* __restrict__ bm,
    const float* __restrict__ Wv, const float* __restrict__ bv,
    int M)
{
    extern __shared__ float smem[];

    int nb   = blockIdx.x & 1;
    int path = blockIdx.x >> 1;
    const float* W    = path ? Wv : Wm;
    const float* bias = path ? bv : bm;
    float* H          = path ? g_Hv : g_Hm;

    int rowBase = blockIdx.y * 128;
    int t = threadIdx.x, wid = t >> 5, lane = t & 31;
    int warpM = wid >> 2, warpN = wid & 3;
    int lr = lane >> 2, lc = lane & 3;

    int mA0 = t >> 2,        kqA = t & 3;
    int mA1 = (t + 256) >> 2;
    int k2B0 = t >> 5,       nqB = t & 31;
    int k2B1 = (t + 256) >> 5;
    int szA0 = (rowBase + mA0 < M) ? 16 : 0;
    int szA1 = (rowBase + mA1 < M) ? 16 : 0;
    const float* XA0 = X + (size_t)(rowBase + mA0) * FIN + kqA * 4;
    const float* XA1 = X + (size_t)(rowBase + mA1) * FIN + kqA * 4;
    const float* WB0 = W + (size_t)k2B0 * HID + nb * 128 + nqB * 4;
    const float* WB1 = W + (size_t)k2B1 * HID + nb * 128 + nqB * 4;
    uint32_t dA0 = smem_u32(&smem[mA0 * G0_ASTR + kqA * 4]);
    uint32_t dA1 = smem_u32(&smem[mA1 * G0_ASTR + kqA * 4]);
    uint32_t dB0 = smem_u32(&smem[128 * G0_ASTR + k2B0 * G0_BSTR + nqB * 4]);
    uint32_t dB1 = smem_u32(&smem[128 * G0_ASTR + k2B1 * G0_BSTR + nqB * 4]);

    float acc[4][4][4];
    #pragma unroll
    for (int i = 0; i < 4; i++)
        #pragma unroll
        for (int j = 0; j < 4; j++)
            #pragma unroll
            for (int q = 0; q < 4; q++) acc[i][j][q] = 0.0f;

    // prologue: stages 0,1
    #pragma unroll
    for (int pc = 0; pc < 2; pc++) {
        uint32_t so = pc * G0_STAGE * 4;
        cp_async16(dA0 + so, XA0 + pc * 16, szA0);
        cp_async16(dA1 + so, XA1 + pc * 16, szA1);
        cp_async16(dB0 + so, WB0 + (size_t)pc * 16 * HID, 16);
        cp_async16(dB1 + so, WB1 + (size_t)pc * 16 * HID, 16);
        cp_commit();
    }

    for (int c = 0; c < 32; c++) {
        if (c < 30) cp_wait1(); else cp_wait0();
        __syncthreads();

        int cur = c - (c / 3) * 3;   // c % 3
        const float* sA = smem + cur * G0_STAGE;
        const float* sB = sA + 128 * G0_ASTR;

        #pragma unroll
        for (int ks = 0; ks < 2; ks++) {
            int kb = ks * 8;
            uint32_t afr[4][4];
            #pragma unroll
            for (int mt = 0; mt < 4; mt++) {
                int m0 = warpM * 64 + mt * 16 + lr;
                afr[mt][0] = __float_as_uint(sA[m0 * G0_ASTR + kb + lc]);
                afr[mt][1] = __float_as_uint(sA[(m0 + 8) * G0_ASTR + kb + lc]);
                afr[mt][2] = __float_as_uint(sA[m0 * G0_ASTR + kb + lc + 4]);
                afr[mt][3] = __float_as_uint(sA[(m0 + 8) * G0_ASTR + kb + lc + 4]);
            }
            #pragma unroll
            for (int nt = 0; nt < 4; nt++) {
                int n0 = warpN * 32 + nt * 8 + lr;
                uint32_t bfr[2];
                bfr[0] = __float_as_uint(sB[(kb + lc) * G0_BSTR + n0]);
                bfr[1] = __float_as_uint(sB[(kb + lc + 4) * G0_BSTR + n0]);
                #pragma unroll
                for (int mt = 0; mt < 4; mt++) mma_tf32(acc[mt][nt], afr[mt], bfr);
            }
        }

        if (c + 2 < 32) {
            int cn = c + 2;
            int s  = cn - (cn / 3) * 3;
            uint32_t so = s * G0_STAGE * 4;
            cp_async16(dA0 + so, XA0 + cn * 16, szA0);
            cp_async16(dA1 + so, XA1 + cn * 16, szA1);
            cp_async16(dB0 + so, WB0 + (size_t)cn * 16 * HID, 16);
            cp_async16(dB1 + so, WB1 + (size_t)cn * 16 * HID, 16);
            cp_commit();
        }
    }

    // epilogue: bias + activation, fp32 store
    #pragma unroll
    for (int mt = 0; mt < 4; mt++) {
        int r0 = rowBase + warpM * 64 + mt * 16 + lr;
        #pragma unroll
        for (int nt = 0; nt < 4; nt++) {
            int cb = nb * 128 + warpN * 32 + nt * 8 + lc * 2;
            float b0 = bias[cb], b1 = bias[cb + 1];
            #pragma unroll
            for (int half = 0; half < 2; half++) {
                int r = r0 + half * 8;
                if (r >= M) continue;
                float v0 = acc[mt][nt][half * 2 + 0] + b0;
                float v1 = acc[mt][nt][half * 2 + 1] + b1;
                if (path == 0) {
                    v0 = (v0 > 0.0f) ? v0 : expm1f(v0);
                    v1 = (v1 > 0.0f) ? v1 : expm1f(v1);
                } else {
                    v0 = fmaxf(v0, 0.0f);
                    v1 = fmaxf(v1, 0.0f);
                }
                *(float2*)(H + (size_t)r * HID + cb) = make_float2(v0, v1);
            }
        }
    }
}

// ---------------- layer-1 via tf32 HMMA, cp.async 3-stage ------------------------
// BM=128, BN=64, K=256 per path; both paths sequential; attn-coupled epilogue
// writing bf16x2-packed m64b/v64b.
#define L1_ASTR 20
#define L1_BSTR 72
#define L1_STAGE (128 * L1_ASTR + 16 * L1_BSTR)   // 3712 floats
#define L1_SMEM  (3 * L1_STAGE * 4)               // 44544 bytes

__global__ __launch_bounds__(256, 2) void layer1_mma_kernel(
    const float* __restrict__ Wm1, const float* __restrict__ bm1,
    const float* __restrict__ Wv1, const float* __restrict__ bv1,
    int M)
{
    extern __shared__ float smem[];

    int rowBase = blockIdx.x * 128;
    int t = threadIdx.x, wid = t >> 5, lane = t & 31;
    int warpM = wid >> 2, warpN = wid & 3;
    int lr = lane >> 2, lc = lane & 3;

    int mA0 = t >> 2,        kqA = t & 3;
    int mA1 = (t + 256) >> 2;
    int k2B = t >> 4,        nqB = t & 15;
    int szA0 = (rowBase + mA0 < M) ? 16 : 0;
    int szA1 = (rowBase + mA1 < M) ? 16 : 0;
    uint32_t dA0 = smem_u32(&smem[mA0 * L1_ASTR + kqA * 4]);
    uint32_t dA1 = smem_u32(&smem[mA1 * L1_ASTR + kqA * 4]);
    uint32_t dB  = smem_u32(&smem[128 * L1_ASTR + k2B * L1_BSTR + nqB * 4]);

    float acc0[4][2][4], acc1[4][2][4];
    #pragma unroll
    for (int i = 0; i < 4; i++)
        #pragma unroll
        for (int j = 0; j < 2; j++)
            #pragma unroll
            for (int q = 0; q < 4; q++) { acc0[i][j][q] = 0.f; acc1[i][j][q] = 0.f; }

    #pragma unroll
    for (int p = 0; p < 2; p++) {
        const float* A = p ? g_Hv : g_Hm;
        const float* W = p ? Wv1 : Wm1;
        const float* A0 = A + (size_t)(rowBase + mA0) * HID + kqA * 4;
        const float* A1 = A + (size_t)(rowBase + mA1) * HID + kqA * 4;
        const float* WB = W + (size_t)k2B * CLS + nqB * 4;

        __syncthreads();   // previous path's consumers done before overwrite

        #pragma unroll
        for (int pc = 0; pc < 2; pc++) {
            uint32_t so = pc * L1_STAGE * 4;
            cp_async16(dA0 + so, A0 + pc * 16, szA0);
            cp_async16(dA1 + so, A1 + pc * 16, szA1);
            cp_async16(dB + so, WB + (size_t)pc * 16 * CLS, 16);
            cp_commit();
        }

        for (int c = 0; c < 16; c++) {
            if (c < 14) cp_wait1(); else cp_wait0();
            __syncthreads();

            int cur = c - (c / 3) * 3;
            const float* sA = smem + cur * L1_STAGE;
            const float* sB = sA + 128 * L1_ASTR;

            #pragma unroll
            for (int ks = 0; ks < 2; ks++) {
                int kb = ks * 8;
                uint32_t afr[4][4];
                #pragma unroll
                for (int mt = 0; mt < 4; mt++) {
                    int m0 = warpM * 64 + mt * 16 + lr;
                    afr[mt][0] = __float_as_uint(sA[m0 * L1_ASTR + kb + lc]);
                    afr[mt][1] = __float_as_uint(sA[(m0 + 8) * L1_ASTR + kb + lc]);
                    afr[mt][2] = __float_as_uint(sA[m0 * L1_ASTR + kb + lc + 4]);
                    afr[mt][3] = __float_as_uint(sA[(m0 + 8) * L1_ASTR + kb + lc + 4]);
                }
                #pragma unroll
                for (int nt = 0; nt < 2; nt++) {
                    int n0 = warpN * 16 + nt * 8 + lr;
                    uint32_t bfr[2];
                    bfr[0] = __float_as_uint(sB[(kb + lc) * L1_BSTR + n0]);
                    bfr[1] = __float_as_uint(sB[(kb + lc + 4) * L1_BSTR + n0]);
                    #pragma unroll
                    for (int mt = 0; mt < 4; mt++)
                        mma_tf32(p ? acc1[mt][nt] : acc0[mt][nt], afr[mt], bfr);
                }
            }

            if (c + 2 < 16) {
                int cn = c + 2;
                int s  = cn - (cn / 3) * 3;
                uint32_t so = s * L1_STAGE * 4;
                cp_async16(dA0 + so, A0 + cn * 16, szA0);
                cp_async16(dA1 + so, A1 + cn * 16, szA1);
                cp_async16(dB + so, WB + (size_t)cn * 16 * CLS, 16);
                cp_commit();
            }
        }
    }

    // fused epilogue: elu/relu + attn coupling, write bf16x2-packed m64b/v64b
    #pragma unroll
    for (int mt = 0; mt < 4; mt++) {
        int r0 = rowBase + warpM * 64 + mt * 16 + lr;
        #pragma unroll
        for (int nt = 0; nt < 2; nt++) {
            int cb = warpN * 16 + nt * 8 + lc * 2;
            float bm0c = bm1[cb], bm1c = bm1[cb + 1];
            float bv0c = bv1[cb], bv1c = bv1[cb + 1];
            #pragma unroll
            for (int half = 0; half < 2; half++) {
                int r = r0 + half * 8;
                if (r >= M) continue;
                float m0 = acc0[mt][nt][half * 2 + 0] + bm0c;
                float m1 = acc0[mt][nt][half * 2 + 1] + bm1c;
                m0 = (m0 > 0.0f) ? m0 : expm1f(m0);
                m1 = (m1 > 0.0f) ? m1 : expm1f(m1);
                float v0 = fmaxf(acc1[mt][nt][half * 2 + 0] + bv0c, 0.0f) + 1e-6f;
                float v1 = fmaxf(acc1[mt][nt][half * 2 + 1] + bv1c, 0.0f) + 1e-6f;
                float a0 = expf(-v0), a1 = expf(-v1);
                __nv_bfloat162 pm = __float22bfloat162_rn(make_float2(m0 * a0, m1 * a1));
                __nv_bfloat162 pv = __float22bfloat162_rn(make_float2(v0 * a0 * a0, v1 * a1 * a1));
                size_t o = (size_t)r * 32 + (cb >> 1);
                g_m64b[o] = *(uint32_t*)&pm;
                g_v64b[o] = *(uint32_t*)&pv;
            }
        }
    }
}

// ---------------- fused SpMM (CSR, bf16 gather, no atomics) + finalize -----------
// warp per node; lane holds cols (2*lane, 2*lane+1).
__global__ __launch_bounds__(256) void spmm_fused_kernel(
    const float* __restrict__ sample, float* __restrict__ out, int n)
{
    int s    = (blockIdx.x * 256 + threadIdx.x) >> 5;
    int lane = threadIdx.x & 31;
    if (s >= n) return;

    float dis_s = g_dis[s], di_s = g_di[s];
    int start = g_rowstart[s];
    int cnt   = g_ecnt[s];

    // self-loop contribution
    float2 msl = __bfloat1622float2(*(__nv_bfloat162*)&g_m64b[(size_t)s * 32 + lane]);
    float2 vsl = __bfloat1622float2(*(__nv_bfloat162*)&g_v64b[(size_t)s * 32 + lane]);
    float am0 = dis_s * dis_s * msl.x;
    float am1 = dis_s * dis_s * msl.y;
    float av0 = di_s * di_s * vsl.x;
    float av1 = di_s * di_s * vsl.y;

    int j = 0;
    for (; j + 4 <= cnt; j += 4) {
        int d0 = g_eidx[start + j];
        int d1 = g_eidx[start + j + 1];
        int d2 = g_eidx[start + j + 2];
        int d3 = g_eidx[start + j + 3];
        float wm0 = dis_s * g_dis[d0], wv0 = di_s * g_di[d0];
        float wm1 = dis_s * g_dis[d1], wv1 = di_s * g_di[d1];
        float wm2 = dis_s * g_dis[d2], wv2 = di_s * g_di[d2];
        float wm3 = dis_s * g_dis[d3], wv3 = di_s * g_di[d3];
        uint32_t mu0 = g_m64b[(size_t)d0 * 32 + lane];
        uint32_t mu1 = g_m64b[(size_t)d1 * 32 + lane];
        uint32_t mu2 = g_m64b[(size_t)d2 * 32 + lane];
        uint32_t mu3 = g_m64b[(size_t)d3 * 32 + lane];
        uint32_t vu0 = g_v64b[(size_t)d0 * 32 + lane];
        uint32_t vu1 = g_v64b[(size_t)d1 * 32 + lane];
        uint32_t vu2 = g_v64b[(size_t)d2 * 32 + lane];
        uint32_t vu3 = g_v64b[(size_t)d3 * 32 + lane];
        float2 m0 = __bfloat1622float2(*(__nv_bfloat162*)&mu0);
        float2 m1 = __bfloat1622float2(*(__nv_bfloat162*)&mu1);
        float2 m2 = __bfloat1622float2(*(__nv_bfloat162*)&mu2);
        float2 m3 = __bfloat1622float2(*(__nv_bfloat162*)&mu3);
        float2 v0 = __bfloat1622float2(*(__nv_bfloat162*)&vu0);
        float2 v1 = __bfloat1622float2(*(__nv_bfloat162*)&vu1);
        float2 v2 = __bfloat1622float2(*(__nv_bfloat162*)&vu2);
        float2 v3 = __bfloat1622float2(*(__nv_bfloat162*)&vu3);
        am0 += wm0 * m0.x + wm1 * m1.x + wm2 * m2.x + wm3 * m3.x;
        am1 += wm0 * m0.y + wm1 * m1.y + wm2 * m2.y + wm3 * m3.y;
        av0 += wv0 * v0.x + wv1 * v1.x + wv2 * v2.x + wv3 * v3.x;
        av1 += wv0 * v0.y + wv1 * v1.y + wv2 * v2.y + wv3 * v3.y;
    }
    for (; j < cnt; j++) {
        int d = g_eidx[start + j];
        float wm = dis_s * g_dis[d], wv = di_s * g_di[d];
        uint32_t mu = g_m64b[(size_t)d * 32 + lane];
        uint32_t vu = g_v64b[(size_t)d * 32 + lane];
        float2 mm = __bfloat1622float2(*(__nv_bfloat162*)&mu);
        float2 vv = __bfloat1622float2(*(__nv_bfloat162*)&vu);
        am0 += wm * mm.x;
        am1 += wm * mm.y;
        av0 += wv * vv.x;
        av1 += wv * vv.y;
    }

    // finalize: out = m + sample*sqrt(v); log_softmax over 64 (lane pair layout)
    size_t base = (size_t)s * CLS;
    float2 sp = *(const float2*)(sample + base + lane * 2);
    float va = am0 + sp.x * sqrtf(fmaxf(av0, 0.f));
    float vb = am1 + sp.y * sqrtf(fmaxf(av1, 0.f));
    float mx = fmaxf(va, vb);
    #pragma unroll
    for (int o = 16; o; o >>= 1) mx = fmaxf(mx, __shfl_xor_sync(0xFFFFFFFFu, mx, o));
    float sum = expf(va - mx) + expf(vb - mx);
    #pragma unroll
    for (int o = 16; o; o >>= 1) sum += __shfl_xor_sync(0xFFFFFFFFu, sum, o);
    float lse = mx + logf(sum);
    *(float2*)(out + base + lane * 2) = make_float2(va - lse, vb - lse);
}

// ---------------- launch ----------------
extern "C" void kernel_launch(void* const* d_in, const int* in_sizes, int n_in,
                              void* d_out, int out_size)
{
    const float* x      = (const float*)d_in[0];
    const float* Wm0    = (const float*)d_in[1];
    const float* bm0    = (const float*)d_in[2];
    const float* Wv0    = (const float*)d_in[3];
    const float* bv0    = (const float*)d_in[4];
    const float* Wm1    = (const float*)d_in[5];
    const float* bm1    = (const float*)d_in[6];
    const float* Wv1    = (const float*)d_in[7];
    const float* bv1    = (const float*)d_in[8];
    const float* sample = (const float*)d_in[9];
    const int*   esrc   = (const int*)d_in[10];
    const int*   edst   = (const int*)d_in[11];
    float* out = (float*)d_out;

    int M = in_sizes[0] / FIN;     // 100000
    int E = in_sizes[10];          // 3200000
    if (M > NNODE) M = NNODE;
    if (E > MAXE)  E = MAXE;
    int nblk = (M + 1023) / 1024;

    cudaFuncSetAttribute(gemm0_mma_kernel, cudaFuncAttributeMaxDynamicSharedMemorySize, G0_SMEM);
    cudaFuncSetAttribute(layer1_mma_kernel, cudaFuncAttributeMaxDynamicSharedMemorySize, L1_SMEM);

    // degree + CSR build
    zero_ecnt_kernel    <<<(M + 255) / 256, 256>>>(M);
    count_edges_kernel  <<<(E + 255) / 256, 256>>>(esrc, E);
    scan_blocks_kernel  <<<nblk, 1024>>>(M);
    scan_tops_kernel    <<<1, 128>>>(nblk);
    scan_add_deg_kernel <<<(M + 255) / 256, 256>>>(M);
    scatter_edges_kernel<<<(E + 255) / 256, 256>>>(esrc, edst, E);

    // dense pipeline
    dim3 g0(4, (M + 127) / 128);
    gemm0_mma_kernel<<<g0, 256, G0_SMEM>>>(x, Wm0, bm0, Wv0, bv0, M);
    layer1_mma_kernel<<<(M + 127) / 128, 256, L1_SMEM>>>(Wm1, bm1, Wv1, bv1, M);

    // graph aggregation + output
    spmm_fused_kernel<<<((size_t)M * 32 + 255) / 256, 256>>>(sample, out, M);
}

// round 15
// speedup vs baseline: 1.6186x; 1.0887x over previous
#include <cuda_runtime.h>
#include <cuda_bf16.h>
#include <math.h>
#include <stdint.h>

#define NNODE 100000
#define MAXE  3400000
#define FIN   512
#define HID   256
#define CLS   64

// ---------------- scratch (static device globals; no allocation) ----------------
__device__ float    g_Hm[(size_t)NNODE * HID];   // elu(x@Wm0+bm0)
__device__ float    g_Hv[(size_t)NNODE * HID];   // relu(x@Wv0+bv0)
__device__ uint32_t g_m64b[(size_t)NNODE * 32];  // mean*attn, bf16x2 packed
__device__ uint32_t g_v64b[(size_t)NNODE * 32];  // var*attn^2, bf16x2 packed
__device__ int      g_ecnt[NNODE];               // out-degree (no self loop)
__device__ int      g_rowstart[NNODE];           // CSR row starts
__device__ int      g_fill[NNODE];               // scatter cursors
__device__ int      g_bsums[128];                // scan block sums
__device__ int      g_eidx[MAXE];                // CSR dst indices
__device__ float2   g_w2[NNODE];                 // (deg^-0.5, deg^-1)

// ---------------- degree + CSR build ----------------
__global__ void zero_ecnt_kernel(int n) {
    int i = blockIdx.x * blockDim.x + threadIdx.x;
    if (i < n) g_ecnt[i] = 0;
}
__global__ void count_edges_kernel(const int* __restrict__ src, int e) {
    int i = blockIdx.x * blockDim.x + threadIdx.x;
    if (i < e) atomicAdd(&g_ecnt[src[i]], 1);
}
__global__ __launch_bounds__(1024) void scan_blocks_kernel(int n) {
    __shared__ int sh[1024];
    int tid = threadIdx.x;
    int gid = blockIdx.x * 1024 + tid;
    int v = (gid < n) ? g_ecnt[gid] : 0;
    sh[tid] = v;
    __syncthreads();
    for (int off = 1; off < 1024; off <<= 1) {
        int t = (tid >= off) ? sh[tid - off] : 0;
        __syncthreads();
        sh[tid] += t;
        __syncthreads();
    }
    if (gid < n) g_rowstart[gid] = sh[tid] - v;   // exclusive
    if (tid == 1023) g_bsums[blockIdx.x] = sh[1023];
}
__global__ void scan_tops_kernel(int nblk) {
    __shared__ int sh[128];
    int tid = threadIdx.x;
    int v = (tid < nblk) ? g_bsums[tid] : 0;
    sh[tid] = v;
    __syncthreads();
    for (int off = 1; off < 128; off <<= 1) {
        int t = (tid >= off) ? sh[tid - off] : 0;
        __syncthreads();
        sh[tid] += t;
        __syncthreads();
    }
    if (tid < nblk) g_bsums[tid] = sh[tid] - v;   // exclusive
}
// scan finalize + packed degree weights (fused)
__global__ void scan_add_deg_kernel(int n) {
    int i = blockIdx.x * blockDim.x + threadIdx.x;
    if (i < n) {
        int rs = g_rowstart[i] + g_bsums[i >> 10];
        g_rowstart[i] = rs;
        g_fill[i] = rs;
        float c = (float)(g_ecnt[i] + 1);   // + self loop
        g_w2[i] = make_float2(1.0f / sqrtf(c), 1.0f / c);
    }
}
__global__ void scatter_edges_kernel(const int* __restrict__ src,
                                     const int* __restrict__ dst, int e) {
    int i = blockIdx.x * blockDim.x + threadIdx.x;
    if (i < e) {
        int pos = atomicAdd(&g_fill[src[i]], 1);
        g_eidx[pos] = dst[i];
    }
}

// ---------------- mma.sync + cp.async helpers (legal at compute_103) ------------
__device__ __forceinline__ void mma_tf32(float* c, const uint32_t* a, const uint32_t* b) {
    asm volatile(
        "mma.sync.aligned.m16n8k8.row.col.f32.tf32.tf32.f32 "
        "{%0,%1,%2,%3}, {%4,%5,%6,%7}, {%8,%9}, {%0,%1,%2,%3};"
        : "+f"(c[0]), "+f"(c[1]), "+f"(c[2]), "+f"(c[3])
        : "r"(a[0]), "r"(a[1]), "r"(a[2]), "r"(a[3]), "r"(b[0]), "r"(b[1]));
}
__device__ __forceinline__ uint32_t smem_u32(const void* p) {
    uint32_t a;
    asm("{ .reg .u64 t; cvta.to.shared.u64 t, %1; cvt.u32.u64 %0, t; }" : "=r"(a) : "l"(p));
    return a;
}
__device__ __forceinline__ void cp_async16(uint32_t dst, const void* src, int srcsize) {
    asm volatile("cp.async.cg.shared.global [%0], [%1], 16, %2;"
                 :: "r"(dst), "l"(src), "r"(srcsize) : "memory");
}
__device__ __forceinline__ void cp_commit() {
    asm volatile("cp.async.commit_group;" ::: "memory");
}
__device__ __forceinline__ void cp_wait1() {
    asm volatile("cp.async.wait_group 1;" ::: "memory");
}
__device__ __forceinline__ void cp_wait0() {
    asm volatile("cp.async.wait_group 0;" ::: "memory");
}

// ---------------- layer-0 GEMM: H = act(X @ W + b), cp.async 3-stage -------------
// BM=128, BN=128, BK=16, 256 thr (8 warps 2x4), warp tile 64x32.  (R7/R10-proven)
#define G0_ASTR 20
#define G0_BSTR 136
#define G0_STAGE (128 * G0_ASTR + 16 * G0_BSTR)   // 4736 floats
#define G0_SMEM  (3 * G0_STAGE * 4)               // 56832 bytes

__global__ __launch_bounds__(256, 2) void gemm0_mma_kernel(
    const float* __restrict__ X,
    const float* __restrict__ Wm, const float* __restrict__ bm,
    const float* __restrict__ Wv, const float* __restrict__ bv,
    int M)
{
    extern __shared__ float smem[];

    int nb   = blockIdx.x & 1;
    int path = blockIdx.x >> 1;
    const float* W    = path ? Wv : Wm;
    const float* bias = path ? bv : bm;
    float* H          = path ? g_Hv : g_Hm;

    int rowBase = blockIdx.y * 128;
    int t = threadIdx.x, wid = t >> 5, lane = t & 31;
    int warpM = wid >> 2, warpN = wid & 3;
    int lr = lane >> 2, lc = lane & 3;

    int mA0 = t >> 2,        kqA = t & 3;
    int mA1 = (t + 256) >> 2;
    int k2B0 = t >> 5,       nqB = t & 31;
    int k2B1 = (t + 256) >> 5;
    int szA0 = (rowBase + mA0 < M) ? 16 : 0;
    int szA1 = (rowBase + mA1 < M) ? 16 : 0;
    const float* XA0 = X + (size_t)(rowBase + mA0) * FIN + kqA * 4;
    const float* XA1 = X + (size_t)(rowBase + mA1) * FIN + kqA * 4;
    const float* WB0 = W + (size_t)k2B0 * HID + nb * 128 + nqB * 4;
    const float* WB1 = W + (size_t)k2B1 * HID + nb * 128 + nqB * 4;
    uint32_t dA0 = smem_u32(&smem[mA0 * G0_ASTR + kqA * 4]);
    uint32_t dA1 = smem_u32(&smem[mA1 * G0_ASTR + kqA * 4]);
    uint32_t dB0 = smem_u32(&smem[128 * G0_ASTR + k2B0 * G0_BSTR + nqB * 4]);
    uint32_t dB1 = smem_u32(&smem[128 * G0_ASTR + k2B1 * G0_BSTR + nqB * 4]);

    float acc[4][4][4];
    #pragma unroll
    for (int i = 0; i < 4; i++)
        #pragma unroll
        for (int j = 0; j < 4; j++)
            #pragma unroll
            for (int q = 0; q < 4; q++) acc[i][j][q] = 0.0f;

    // prologue: stages 0,1
    #pragma unroll
    for (int pc = 0; pc < 2; pc++) {
        uint32_t so = pc * G0_STAGE * 4;
        cp_async16(dA0 + so, XA0 + pc * 16, szA0);
        cp_async16(dA1 + so, XA1 + pc * 16, szA1);
        cp_async16(dB0 + so, WB0 + (size_t)pc * 16 * HID, 16);
        cp_async16(dB1 + so, WB1 + (size_t)pc * 16 * HID, 16);
        cp_commit();
    }

    for (int c = 0; c < 32; c++) {
        if (c < 30) cp_wait1(); else cp_wait0();
        __syncthreads();

        int cur = c - (c / 3) * 3;   // c % 3
        const float* sA = smem + cur * G0_STAGE;
        const float* sB = sA + 128 * G0_ASTR;

        #pragma unroll
        for (int ks = 0; ks < 2; ks++) {
            int kb = ks * 8;
            uint32_t afr[4][4];
            #pragma unroll
            for (int mt = 0; mt < 4; mt++) {
                int m0 = warpM * 64 + mt * 16 + lr;
                afr[mt][0] = __float_as_uint(sA[m0 * G0_ASTR + kb + lc]);
                afr[mt][1] = __float_as_uint(sA[(m0 + 8) * G0_ASTR + kb + lc]);
                afr[mt][2] = __float_as_uint(sA[m0 * G0_ASTR + kb + lc + 4]);
                afr[mt][3] = __float_as_uint(sA[(m0 + 8) * G0_ASTR + kb + lc + 4]);
            }
            #pragma unroll
            for (int nt = 0; nt < 4; nt++) {
                int n0 = warpN * 32 + nt * 8 + lr;
                uint32_t bfr[2];
                bfr[0] = __float_as_uint(sB[(kb + lc) * G0_BSTR + n0]);
                bfr[1] = __float_as_uint(sB[(kb + lc + 4) * G0_BSTR + n0]);
                #pragma unroll
                for (int mt = 0; mt < 4; mt++) mma_tf32(acc[mt][nt], afr[mt], bfr);
            }
        }

        if (c + 2 < 32) {
            int cn = c + 2;
            int s  = cn - (cn / 3) * 3;
            uint32_t so = s * G0_STAGE * 4;
            cp_async16(dA0 + so, XA0 + cn * 16, szA0);
            cp_async16(dA1 + so, XA1 + cn * 16, szA1);
            cp_async16(dB0 + so, WB0 + (size_t)cn * 16 * HID, 16);
            cp_async16(dB1 + so, WB1 + (size_t)cn * 16 * HID, 16);
            cp_commit();
        }
    }

    // epilogue: bias + activation, fp32 store
    #pragma unroll
    for (int mt = 0; mt < 4; mt++) {
        int r0 = rowBase + warpM * 64 + mt * 16 + lr;
        #pragma unroll
        for (int nt = 0; nt < 4; nt++) {
            int cb = nb * 128 + warpN * 32 + nt * 8 + lc * 2;
            float b0 = bias[cb], b1 = bias[cb + 1];
            #pragma unroll
            for (int half = 0; half < 2; half++) {
                int r = r0 + half * 8;
                if (r >= M) continue;
                float v0 = acc[mt][nt][half * 2 + 0] + b0;
                float v1 = acc[mt][nt][half * 2 + 1] + b1;
                if (path == 0) {
                    v0 = (v0 > 0.0f) ? v0 : expm1f(v0);
                    v1 = (v1 > 0.0f) ? v1 : expm1f(v1);
                } else {
                    v0 = fmaxf(v0, 0.0f);
                    v1 = fmaxf(v1, 0.0f);
                }
                *(float2*)(H + (size_t)r * HID + cb) = make_float2(v0, v1);
            }
        }
    }
}

// ---------------- layer-1 via tf32 HMMA, cp.async 3-stage ------------------------
#define L1_ASTR 20
#define L1_BSTR 72
#define L1_STAGE (128 * L1_ASTR + 16 * L1_BSTR)   // 3712 floats
#define L1_SMEM  (3 * L1_STAGE * 4)               // 44544 bytes

__global__ __launch_bounds__(256, 2) void layer1_mma_kernel(
    const float* __restrict__ Wm1, const float* __restrict__ bm1,
    const float* __restrict__ Wv1, const float* __restrict__ bv1,
    int M)
{
    extern __shared__ float smem[];

    int rowBase = blockIdx.x * 128;
    int t = threadIdx.x, wid = t >> 5, lane = t & 31;
    int warpM = wid >> 2, warpN = wid & 3;
    int lr = lane >> 2, lc = lane & 3;

    int mA0 = t >> 2,        kqA = t & 3;
    int mA1 = (t + 256) >> 2;
    int k2B = t >> 4,        nqB = t & 15;
    int szA0 = (rowBase + mA0 < M) ? 16 : 0;
    int szA1 = (rowBase + mA1 < M) ? 16 : 0;
    uint32_t dA0 = smem_u32(&smem[mA0 * L1_ASTR + kqA * 4]);
    uint32_t dA1 = smem_u32(&smem[mA1 * L1_ASTR + kqA * 4]);
    uint32_t dB  = smem_u32(&smem[128 * L1_ASTR + k2B * L1_BSTR + nqB * 4]);

    float acc0[4][2][4], acc1[4][2][4];
    #pragma unroll
    for (int i = 0; i < 4; i++)
        #pragma unroll
        for (int j = 0; j < 2; j++)
            #pragma unroll
            for (int q = 0; q < 4; q++) { acc0[i][j][q] = 0.f; acc1[i][j][q] = 0.f; }

    #pragma unroll
    for (int p = 0; p < 2; p++) {
        const float* A = p ? g_Hv : g_Hm;
        const float* W = p ? Wv1 : Wm1;
        const float* A0 = A + (size_t)(rowBase + mA0) * HID + kqA * 4;
        const float* A1 = A + (size_t)(rowBase + mA1) * HID + kqA * 4;
        const float* WB = W + (size_t)k2B * CLS + nqB * 4;

        __syncthreads();   // previous path's consumers done before overwrite

        #pragma unroll
        for (int pc = 0; pc < 2; pc++) {
            uint32_t so = pc * L1_STAGE * 4;
            cp_async16(dA0 + so, A0 + pc * 16, szA0);
            cp_async16(dA1 + so, A1 + pc * 16, szA1);
            cp_async16(dB + so, WB + (size_t)pc * 16 * CLS, 16);
            cp_commit();
        }

        for (int c = 0; c < 16; c++) {
            if (c < 14) cp_wait1(); else cp_wait0();
            __syncthreads();

            int cur = c - (c / 3) * 3;
            const float* sA = smem + cur * L1_STAGE;
            const float* sB = sA + 128 * L1_ASTR;

            #pragma unroll
            for (int ks = 0; ks < 2; ks++) {
                int kb = ks * 8;
                uint32_t afr[4][4];
                #pragma unroll
                for (int mt = 0; mt < 4; mt++) {
                    int m0 = warpM * 64 + mt * 16 + lr;
                    afr[mt][0] = __float_as_uint(sA[m0 * L1_ASTR + kb + lc]);
                    afr[mt][1] = __float_as_uint(sA[(m0 + 8) * L1_ASTR + kb + lc]);
                    afr[mt][2] = __float_as_uint(sA[m0 * L1_ASTR + kb + lc + 4]);
                    afr[mt][3] = __float_as_uint(sA[(m0 + 8) * L1_ASTR + kb + lc + 4]);
                }
                #pragma unroll
                for (int nt = 0; nt < 2; nt++) {
                    int n0 = warpN * 16 + nt * 8 + lr;
                    uint32_t bfr[2];
                    bfr[0] = __float_as_uint(sB[(kb + lc) * L1_BSTR + n0]);
                    bfr[1] = __float_as_uint(sB[(kb + lc + 4) * L1_BSTR + n0]);
                    #pragma unroll
                    for (int mt = 0; mt < 4; mt++)
                        mma_tf32(p ? acc1[mt][nt] : acc0[mt][nt], afr[mt], bfr);
                }
            }

            if (c + 2 < 16) {
                int cn = c + 2;
                int s  = cn - (cn / 3) * 3;
                uint32_t so = s * L1_STAGE * 4;
                cp_async16(dA0 + so, A0 + cn * 16, szA0);
                cp_async16(dA1 + so, A1 + cn * 16, szA1);
                cp_async16(dB + so, WB + (size_t)cn * 16 * CLS, 16);
                cp_commit();
            }
        }
    }

    // fused epilogue: elu/relu + attn coupling, write bf16x2-packed m64b/v64b
    #pragma unroll
    for (int mt = 0; mt < 4; mt++) {
        int r0 = rowBase + warpM * 64 + mt * 16 + lr;
        #pragma unroll
        for (int nt = 0; nt < 2; nt++) {
            int cb = warpN * 16 + nt * 8 + lc * 2;
            float bm0c = bm1[cb], bm1c = bm1[cb + 1];
            float bv0c = bv1[cb], bv1c = bv1[cb + 1];
            #pragma unroll
            for (int half = 0; half < 2; half++) {
                int r = r0 + half * 8;
                if (r >= M) continue;
                float m0 = acc0[mt][nt][half * 2 + 0] + bm0c;
                float m1 = acc0[mt][nt][half * 2 + 1] + bm1c;
                m0 = (m0 > 0.0f) ? m0 : expm1f(m0);
                m1 = (m1 > 0.0f) ? m1 : expm1f(m1);
                float v0 = fmaxf(acc1[mt][nt][half * 2 + 0] + bv0c, 0.0f) + 1e-6f;
                float v1 = fmaxf(acc1[mt][nt][half * 2 + 1] + bv1c, 0.0f) + 1e-6f;
                float a0 = expf(-v0), a1 = expf(-v1);
                __nv_bfloat162 pm = __float22bfloat162_rn(make_float2(m0 * a0, m1 * a1));
                __nv_bfloat162 pv = __float22bfloat162_rn(make_float2(v0 * a0 * a0, v1 * a1 * a1));
                size_t o = (size_t)r * 32 + (cb >> 1);
                g_m64b[o] = *(uint32_t*)&pm;
                g_v64b[o] = *(uint32_t*)&pv;
            }
        }
    }
}

// ---------------- fused SpMM (CSR, bf16 gather, unroll 8) + finalize -------------
// warp per node; lane holds cols (2*lane, 2*lane+1).
__global__ __launch_bounds__(256) void spmm_fused_kernel(
    const float* __restrict__ sample, float* __restrict__ out, int n)
{
    int s    = (blockIdx.x * 256 + threadIdx.x) >> 5;
    int lane = threadIdx.x & 31;
    if (s >= n) return;

    float2 ws = g_w2[s];
    int start = g_rowstart[s];
    int cnt   = g_ecnt[s];

    // self-loop contribution
    float2 msl = __bfloat1622float2(*(__nv_bfloat162*)&g_m64b[(size_t)s * 32 + lane]);
    float2 vsl = __bfloat1622float2(*(__nv_bfloat162*)&g_v64b[(size_t)s * 32 + lane]);
    float am0 = ws.x * ws.x * msl.x;
    float am1 = ws.x * ws.x * msl.y;
    float av0 = ws.y * ws.y * vsl.x;
    float av1 = ws.y * ws.y * vsl.y;

    int j = 0;
    for (; j + 8 <= cnt; j += 8) {
        int d[8];
        #pragma unroll
        for (int q = 0; q < 8; q++) d[q] = g_eidx[start + j + q];
        float2 w[8];
        #pragma unroll
        for (int q = 0; q < 8; q++) w[q] = g_w2[d[q]];
        uint32_t mu[8], vu[8];
        #pragma unroll
        for (int q = 0; q < 8; q++) mu[q] = g_m64b[(size_t)d[q] * 32 + lane];
        #pragma unroll
        for (int q = 0; q < 8; q++) vu[q] = g_v64b[(size_t)d[q] * 32 + lane];
        #pragma unroll
        for (int q = 0; q < 8; q++) {
            float wm = ws.x * w[q].x;
            float wv = ws.y * w[q].y;
            float2 mm = __bfloat1622float2(*(__nv_bfloat162*)&mu[q]);
            float2 vv = __bfloat1622float2(*(__nv_bfloat162*)&vu[q]);
            am0 += wm * mm.x;
            am1 += wm * mm.y;
            av0 += wv * vv.x;
            av1 += wv * vv.y;
        }
    }
    for (; j < cnt; j++) {
        int d = g_eidx[start + j];
        float2 w = g_w2[d];
        float wm = ws.x * w.x, wv = ws.y * w.y;
        uint32_t mu = g_m64b[(size_t)d * 32 + lane];
        uint32_t vu = g_v64b[(size_t)d * 32 + lane];
        float2 mm = __bfloat1622float2(*(__nv_bfloat162*)&mu);
        float2 vv = __bfloat1622float2(*(__nv_bfloat162*)&vu);
        am0 += wm * mm.x;
        am1 += wm * mm.y;
        av0 += wv * vv.x;
        av1 += wv * vv.y;
    }

    // finalize: out = m + sample*sqrt(v); log_softmax over 64 (lane pair layout)
    size_t base = (size_t)s * CLS;
    float2 sp = *(const float2*)(sample + base + lane * 2);
    float va = am0 + sp.x * sqrtf(fmaxf(av0, 0.f));
    float vb = am1 + sp.y * sqrtf(fmaxf(av1, 0.f));
    float mx = fmaxf(va, vb);
    #pragma unroll
    for (int o = 16; o; o >>= 1) mx = fmaxf(mx, __shfl_xor_sync(0xFFFFFFFFu, mx, o));
    float sum = expf(va - mx) + expf(vb - mx);
    #pragma unroll
    for (int o = 16; o; o >>= 1) sum += __shfl_xor_sync(0xFFFFFFFFu, sum, o);
    float lse = mx + logf(sum);
    *(float2*)(out + base + lane * 2) = make_float2(va - lse, vb - lse);
}

// ---------------- launch ----------------
extern "C" void kernel_launch(void* const* d_in, const int* in_sizes, int n_in,
                              void* d_out, int out_size)
{
    const float* x      = (const float*)d_in[0];
    const float* Wm0    = (const float*)d_in[1];
    const float* bm0    = (const float*)d_in[2];
    const float* Wv0    = (const float*)d_in[3];
    const float* bv0    = (const float*)d_in[4];
    const float* Wm1    = (const float*)d_in[5];
    const float* bm1    = (const float*)d_in[6];
    const float* Wv1    = (const float*)d_in[7];
    const float* bv1    = (const float*)d_in[8];
    const float* sample = (const float*)d_in[9];
    const int*   esrc   = (const int*)d_in[10];
    const int*   edst   = (const int*)d_in[11];
    float* out = (float*)d_out;

    int M = in_sizes[0] / FIN;     // 100000
    int E = in_sizes[10];          // 3200000
    if (M > NNODE) M = NNODE;
    if (E > MAXE)  E = MAXE;
    int nblk = (M + 1023) / 1024;

    // one-time infra (created on the uncaptured correctness call; capture only
    // sees launches + event edges — no allocation, no work change)
    static cudaStream_t sB = nullptr;
    static cudaEvent_t evF = nullptr, evB = nullptr;
    if (sB == nullptr) {
        cudaStreamCreateWithFlags(&sB, cudaStreamNonBlocking);
        cudaEventCreateWithFlags(&evF, cudaEventDisableTiming);
        cudaEventCreateWithFlags(&evB, cudaEventDisableTiming);
    }

    cudaFuncSetAttribute(gemm0_mma_kernel, cudaFuncAttributeMaxDynamicSharedMemorySize, G0_SMEM);
    cudaFuncSetAttribute(layer1_mma_kernel, cudaFuncAttributeMaxDynamicSharedMemorySize, L1_SMEM);

    // fork: CSR build on sB, dense pipeline on default stream
    cudaEventRecord(evF, 0);
    cudaStreamWaitEvent(sB, evF, 0);

    zero_ecnt_kernel    <<<(M + 255) / 256, 256, 0, sB>>>(M);
    count_edges_kernel  <<<(E + 255) / 256, 256, 0, sB>>>(esrc, E);
    scan_blocks_kernel  <<<nblk, 1024, 0, sB>>>(M);
    scan_tops_kernel    <<<1, 128, 0, sB>>>(nblk);
    scan_add_deg_kernel <<<(M + 255) / 256, 256, 0, sB>>>(M);
    scatter_edges_kernel<<<(E + 255) / 256, 256, 0, sB>>>(esrc, edst, E);
    cudaEventRecord(evB, sB);

    // dense pipeline (independent of CSR build)
    dim3 g0(4, (M + 127) / 128);
    gemm0_mma_kernel<<<g0, 256, G0_SMEM>>>(x, Wm0, bm0, Wv0, bv0, M);
    layer1_mma_kernel<<<(M + 127) / 128, 256, L1_SMEM>>>(Wm1, bm1, Wv1, bv1, M);

    // join: spmm needs CSR + layer1 output
    cudaStreamWaitEvent(0, evB, 0);
    spmm_fused_kernel<<<((size_t)M * 32 + 255) / 256, 256>>>(sample, out, M);
}

// round 16
// speedup vs baseline: 1.6546x; 1.0223x over previous
#include <cuda_runtime.h>
#include <cuda_bf16.h>
#include <math.h>
#include <stdint.h>

#define NNODE 100000
#define MAXE  4000000
#define FIN   512
#define HID   256
#define CLS   64

// ---------------- scratch (static device globals; no allocation) ----------------
__device__ float    g_Hm[(size_t)NNODE * HID];   // elu(x@Wm0+bm0)
__device__ float    g_Hv[(size_t)NNODE * HID];   // relu(x@Wv0+bv0)
__device__ uint32_t g_m64b[(size_t)NNODE * 32];  // dis[d]*mean*attn, bf16x2 packed
__device__ uint32_t g_v64b[(size_t)NNODE * 32];  // di[d]*var*attn^2, bf16x2 packed
__device__ int      g_ecnt[NNODE];               // out-degree (no self loop)
__device__ int      g_rowstart[NNODE];           // CSR row starts (8-padded)
__device__ int      g_fill[NNODE];               // scatter cursors
__device__ int      g_bsums[128];                // scan block sums
__device__ int      g_eidx[MAXE];                // CSR dst indices
__device__ float2   g_w2[NNODE];                 // (deg^-0.5, deg^-1)

// ---------------- degree + CSR build ----------------
__global__ void zero_ecnt_kernel(int n) {
    int i = blockIdx.x * blockDim.x + threadIdx.x;
    if (i < n) g_ecnt[i] = 0;
}
__global__ void count_edges_kernel(const int* __restrict__ src, int e) {
    int i = blockIdx.x * blockDim.x + threadIdx.x;
    if (i < e) atomicAdd(&g_ecnt[src[i]], 1);
}
// scan over 8-PADDED counts so every row start is 8-aligned (32B) for int4 loads
__global__ __launch_bounds__(1024) void scan_blocks_kernel(int n) {
    __shared__ int sh[1024];
    int tid = threadIdx.x;
    int gid = blockIdx.x * 1024 + tid;
    int v = (gid < n) ? ((g_ecnt[gid] + 7) & ~7) : 0;
    sh[tid] = v;
    __syncthreads();
    for (int off = 1; off < 1024; off <<= 1) {
        int t = (tid >= off) ? sh[tid - off] : 0;
        __syncthreads();
        sh[tid] += t;
        __syncthreads();
    }
    if (gid < n) g_rowstart[gid] = sh[tid] - v;   // exclusive
    if (tid == 1023) g_bsums[blockIdx.x] = sh[1023];
}
__global__ void scan_tops_kernel(int nblk) {
    __shared__ int sh[128];
    int tid = threadIdx.x;
    int v = (tid < nblk) ? g_bsums[tid] : 0;
    sh[tid] = v;
    __syncthreads();
    for (int off = 1; off < 128; off <<= 1) {
        int t = (tid >= off) ? sh[tid - off] : 0;
        __syncthreads();
        sh[tid] += t;
        __syncthreads();
    }
    if (tid < nblk) g_bsums[tid] = sh[tid] - v;   // exclusive
}
// scan finalize + packed degree weights (fused)
__global__ void scan_add_deg_kernel(int n) {
    int i = blockIdx.x * blockDim.x + threadIdx.x;
    if (i < n) {
        int rs = g_rowstart[i] + g_bsums[i >> 10];
        g_rowstart[i] = rs;
        g_fill[i] = rs;
        float c = (float)(g_ecnt[i] + 1);   // + self loop
        g_w2[i] = make_float2(1.0f / sqrtf(c), 1.0f / c);
    }
}
__global__ void scatter_edges_kernel(const int* __restrict__ src,
                                     const int* __restrict__ dst, int e) {
    int i = blockIdx.x * blockDim.x + threadIdx.x;
    if (i < e) {
        int pos = atomicAdd(&g_fill[src[i]], 1);
        g_eidx[pos] = dst[i];
    }
}

// ---------------- mma.sync + cp.async helpers (legal at compute_103) ------------
__device__ __forceinline__ void mma_tf32(float* c, const uint32_t* a, const uint32_t* b) {
    asm volatile(
        "mma.sync.aligned.m16n8k8.row.col.f32.tf32.tf32.f32 "
        "{%0,%1,%2,%3}, {%4,%5,%6,%7}, {%8,%9}, {%0,%1,%2,%3};"
        : "+f"(c[0]), "+f"(c[1]), "+f"(c[2]), "+f"(c[3])
        : "r"(a[0]), "r"(a[1]), "r"(a[2]), "r"(a[3]), "r"(b[0]), "r"(b[1]));
}
__device__ __forceinline__ uint32_t smem_u32(const void* p) {
    uint32_t a;
    asm("{ .reg .u64 t; cvta.to.shared.u64 t, %1; cvt.u32.u64 %0, t; }" : "=r"(a) : "l"(p));
    return a;
}
__device__ __forceinline__ void cp_async16(uint32_t dst, const void* src, int srcsize) {
    asm volatile("cp.async.cg.shared.global [%0], [%1], 16, %2;"
                 :: "r"(dst), "l"(src), "r"(srcsize) : "memory");
}
__device__ __forceinline__ void cp_commit() {
    asm volatile("cp.async.commit_group;" ::: "memory");
}
__device__ __forceinline__ void cp_wait1() {
    asm volatile("cp.async.wait_group 1;" ::: "memory");
}
__device__ __forceinline__ void cp_wait0() {
    asm volatile("cp.async.wait_group 0;" ::: "memory");
}

// ---------------- layer-0 GEMM: H = act(X @ W + b), cp.async 3-stage -------------
// BM=128, BN=128, BK=16, 256 thr (8 warps 2x4), warp tile 64x32.  (R7/R10-proven)
#define G0_ASTR 20
#define G0_BSTR 136
#define G0_STAGE (128 * G0_ASTR + 16 * G0_BSTR)   // 4736 floats
#define G0_SMEM  (3 * G0_STAGE * 4)               // 56832 bytes

__global__ __launch_bounds__(256, 2) void gemm0_mma_kernel(
    const float* __restrict__ X,
    const float* __restrict__ Wm, const float* __restrict__ bm,
    const float* __restrict__ Wv, const float* __restrict__ bv,
    int M)
{
    extern __shared__ float smem[];

    int nb   = blockIdx.x & 1;
    int path = blockIdx.x >> 1;
    const float* W    = path ? Wv : Wm;
    const float* bias = path ? bv : bm;
    float* H          = path ? g_Hv : g_Hm;

    int rowBase = blockIdx.y * 128;
    int t = threadIdx.x, wid = t >> 5, lane = t & 31;
    int warpM = wid >> 2, warpN = wid & 3;
    int lr = lane >> 2, lc = lane & 3;

    int mA0 = t >> 2,        kqA = t & 3;
    int mA1 = (t + 256) >> 2;
    int k2B0 = t >> 5,       nqB = t & 31;
    int k2B1 = (t + 256) >> 5;
    int szA0 = (rowBase + mA0 < M) ? 16 : 0;
    int szA1 = (rowBase + mA1 < M) ? 16 : 0;
    const float* XA0 = X + (size_t)(rowBase + mA0) * FIN + kqA * 4;
    const float* XA1 = X + (size_t)(rowBase + mA1) * FIN + kqA * 4;
    const float* WB0 = W + (size_t)k2B0 * HID + nb * 128 + nqB * 4;
    const float* WB1 = W + (size_t)k2B1 * HID + nb * 128 + nqB * 4;
    uint32_t dA0 = smem_u32(&smem[mA0 * G0_ASTR + kqA * 4]);
    uint32_t dA1 = smem_u32(&smem[mA1 * G0_ASTR + kqA * 4]);
    uint32_t dB0 = smem_u32(&smem[128 * G0_ASTR + k2B0 * G0_BSTR + nqB * 4]);
    uint32_t dB1 = smem_u32(&smem[128 * G0_ASTR + k2B1 * G0_BSTR + nqB * 4]);

    float acc[4][4][4];
    #pragma unroll
    for (int i = 0; i < 4; i++)
        #pragma unroll
        for (int j = 0; j < 4; j++)
            #pragma unroll
            for (int q = 0; q < 4; q++) acc[i][j][q] = 0.0f;

    #pragma unroll
    for (int pc = 0; pc < 2; pc++) {
        uint32_t so = pc * G0_STAGE * 4;
        cp_async16(dA0 + so, XA0 + pc * 16, szA0);
        cp_async16(dA1 + so, XA1 + pc * 16, szA1);
        cp_async16(dB0 + so, WB0 + (size_t)pc * 16 * HID, 16);
        cp_async16(dB1 + so, WB1 + (size_t)pc * 16 * HID, 16);
        cp_commit();
    }

    for (int c = 0; c < 32; c++) {
        if (c < 30) cp_wait1(); else cp_wait0();
        __syncthreads();

        int cur = c - (c / 3) * 3;   // c % 3
        const float* sA = smem + cur * G0_STAGE;
        const float* sB = sA + 128 * G0_ASTR;

        #pragma unroll
        for (int ks = 0; ks < 2; ks++) {
            int kb = ks * 8;
            uint32_t afr[4][4];
            #pragma unroll
            for (int mt = 0; mt < 4; mt++) {
                int m0 = warpM * 64 + mt * 16 + lr;
                afr[mt][0] = __float_as_uint(sA[m0 * G0_ASTR + kb + lc]);
                afr[mt][1] = __float_as_uint(sA[(m0 + 8) * G0_ASTR + kb + lc]);
                afr[mt][2] = __float_as_uint(sA[m0 * G0_ASTR + kb + lc + 4]);
                afr[mt][3] = __float_as_uint(sA[(m0 + 8) * G0_ASTR + kb + lc + 4]);
            }
            #pragma unroll
            for (int nt = 0; nt < 4; nt++) {
                int n0 = warpN * 32 + nt * 8 + lr;
                uint32_t bfr[2];
                bfr[0] = __float_as_uint(sB[(kb + lc) * G0_BSTR + n0]);
                bfr[1] = __float_as_uint(sB[(kb + lc + 4) * G0_BSTR + n0]);
                #pragma unroll
                for (int mt = 0; mt < 4; mt++) mma_tf32(acc[mt][nt], afr[mt], bfr);
            }
        }

        if (c + 2 < 32) {
            int cn = c + 2;
            int s  = cn - (cn / 3) * 3;
            uint32_t so = s * G0_STAGE * 4;
            cp_async16(dA0 + so, XA0 + cn * 16, szA0);
            cp_async16(dA1 + so, XA1 + cn * 16, szA1);
            cp_async16(dB0 + so, WB0 + (size_t)cn * 16 * HID, 16);
            cp_async16(dB1 + so, WB1 + (size_t)cn * 16 * HID, 16);
            cp_commit();
        }
    }

    #pragma unroll
    for (int mt = 0; mt < 4; mt++) {
        int r0 = rowBase + warpM * 64 + mt * 16 + lr;
        #pragma unroll
        for (int nt = 0; nt < 4; nt++) {
            int cb = nb * 128 + warpN * 32 + nt * 8 + lc * 2;
            float b0 = bias[cb], b1 = bias[cb + 1];
            #pragma unroll
            for (int half = 0; half < 2; half++) {
                int r = r0 + half * 8;
                if (r >= M) continue;
                float v0 = acc[mt][nt][half * 2 + 0] + b0;
                float v1 = acc[mt][nt][half * 2 + 1] + b1;
                if (path == 0) {
                    v0 = (v0 > 0.0f) ? v0 : expm1f(v0);
                    v1 = (v1 > 0.0f) ? v1 : expm1f(v1);
                } else {
                    v0 = fmaxf(v0, 0.0f);
                    v1 = fmaxf(v1, 0.0f);
                }
                *(float2*)(H + (size_t)r * HID + cb) = make_float2(v0, v1);
            }
        }
    }
}

// ---------------- layer-1 via tf32 HMMA, cp.async 3-stage ------------------------
// Epilogue pre-scales payloads by dst degree weights (dis[r], di[r]).
#define L1_ASTR 20
#define L1_BSTR 72
#define L1_STAGE (128 * L1_ASTR + 16 * L1_BSTR)   // 3712 floats
#define L1_SMEM  (3 * L1_STAGE * 4)               // 44544 bytes

__global__ __launch_bounds__(256, 2) void layer1_mma_kernel(
    const float* __restrict__ Wm1, const float* __restrict__ bm1,
    const float* __restrict__ Wv1, const float* __restrict__ bv1,
    int M)
{
    extern __shared__ float smem[];

    int rowBase = blockIdx.x * 128;
    int t = threadIdx.x, wid = t >> 5, lane = t & 31;
    int warpM = wid >> 2, warpN = wid & 3;
    int lr = lane >> 2, lc = lane & 3;

    int mA0 = t >> 2,        kqA = t & 3;
    int mA1 = (t + 256) >> 2;
    int k2B = t >> 4,        nqB = t & 15;
    int szA0 = (rowBase + mA0 < M) ? 16 : 0;
    int szA1 = (rowBase + mA1 < M) ? 16 : 0;
    uint32_t dA0 = smem_u32(&smem[mA0 * L1_ASTR + kqA * 4]);
    uint32_t dA1 = smem_u32(&smem[mA1 * L1_ASTR + kqA * 4]);
    uint32_t dB  = smem_u32(&smem[128 * L1_ASTR + k2B * L1_BSTR + nqB * 4]);

    float acc0[4][2][4], acc1[4][2][4];
    #pragma unroll
    for (int i = 0; i < 4; i++)
        #pragma unroll
        for (int j = 0; j < 2; j++)
            #pragma unroll
            for (int q = 0; q < 4; q++) { acc0[i][j][q] = 0.f; acc1[i][j][q] = 0.f; }

    #pragma unroll
    for (int p = 0; p < 2; p++) {
        const float* A = p ? g_Hv : g_Hm;
        const float* W = p ? Wv1 : Wm1;
        const float* A0 = A + (size_t)(rowBase + mA0) * HID + kqA * 4;
        const float* A1 = A + (size_t)(rowBase + mA1) * HID + kqA * 4;
        const float* WB = W + (size_t)k2B * CLS + nqB * 4;

        __syncthreads();

        #pragma unroll
        for (int pc = 0; pc < 2; pc++) {
            uint32_t so = pc * L1_STAGE * 4;
            cp_async16(dA0 + so, A0 + pc * 16, szA0);
            cp_async16(dA1 + so, A1 + pc * 16, szA1);
            cp_async16(dB + so, WB + (size_t)pc * 16 * CLS, 16);
            cp_commit();
        }

        for (int c = 0; c < 16; c++) {
            if (c < 14) cp_wait1(); else cp_wait0();
            __syncthreads();

            int cur = c - (c / 3) * 3;
            const float* sA = smem + cur * L1_STAGE;
            const float* sB = sA + 128 * L1_ASTR;

            #pragma unroll
            for (int ks = 0; ks < 2; ks++) {
                int kb = ks * 8;
                uint32_t afr[4][4];
                #pragma unroll
                for (int mt = 0; mt < 4; mt++) {
                    int m0 = warpM * 64 + mt * 16 + lr;
                    afr[mt][0] = __float_as_uint(sA[m0 * L1_ASTR + kb + lc]);
                    afr[mt][1] = __float_as_uint(sA[(m0 + 8) * L1_ASTR + kb + lc]);
                    afr[mt][2] = __float_as_uint(sA[m0 * L1_ASTR + kb + lc + 4]);
                    afr[mt][3] = __float_as_uint(sA[(m0 + 8) * L1_ASTR + kb + lc + 4]);
                }
                #pragma unroll
                for (int nt = 0; nt < 2; nt++) {
                    int n0 = warpN * 16 + nt * 8 + lr;
                    uint32_t bfr[2];
                    bfr[0] = __float_as_uint(sB[(kb + lc) * L1_BSTR + n0]);
                    bfr[1] = __float_as_uint(sB[(kb + lc + 4) * L1_BSTR + n0]);
                    #pragma unroll
                    for (int mt = 0; mt < 4; mt++)
                        mma_tf32(p ? acc1[mt][nt] : acc0[mt][nt], afr[mt], bfr);
                }
            }

            if (c + 2 < 16) {
                int cn = c + 2;
                int s  = cn - (cn / 3) * 3;
                uint32_t so = s * L1_STAGE * 4;
                cp_async16(dA0 + so, A0 + cn * 16, szA0);
                cp_async16(dA1 + so, A1 + cn * 16, szA1);
                cp_async16(dB + so, WB + (size_t)cn * 16 * CLS, 16);
                cp_commit();
            }
        }
    }

    // fused epilogue: elu/relu + attn coupling + dst-degree pre-scale, bf16x2 pack
    #pragma unroll
    for (int mt = 0; mt < 4; mt++) {
        int r0 = rowBase + warpM * 64 + mt * 16 + lr;
        #pragma unroll
        for (int nt = 0; nt < 2; nt++) {
            int cb = warpN * 16 + nt * 8 + lc * 2;
            float bm0c = bm1[cb], bm1c = bm1[cb + 1];
            float bv0c = bv1[cb], bv1c = bv1[cb + 1];
            #pragma unroll
            for (int half = 0; half < 2; half++) {
                int r = r0 + half * 8;
                if (r >= M) continue;
                float2 wr = g_w2[r];   // (dis[r], di[r])
                float m0 = acc0[mt][nt][half * 2 + 0] + bm0c;
                float m1 = acc0[mt][nt][half * 2 + 1] + bm1c;
                m0 = (m0 > 0.0f) ? m0 : expm1f(m0);
                m1 = (m1 > 0.0f) ? m1 : expm1f(m1);
                float v0 = fmaxf(acc1[mt][nt][half * 2 + 0] + bv0c, 0.0f) + 1e-6f;
                float v1 = fmaxf(acc1[mt][nt][half * 2 + 1] + bv1c, 0.0f) + 1e-6f;
                float a0 = expf(-v0), a1 = expf(-v1);
                __nv_bfloat162 pm = __float22bfloat162_rn(
                    make_float2(wr.x * m0 * a0, wr.x * m1 * a1));
                __nv_bfloat162 pv = __float22bfloat162_rn(
                    make_float2(wr.y * v0 * a0 * a0, wr.y * v1 * a1 * a1));
                size_t o = (size_t)r * 32 + (cb >> 1);
                g_m64b[o] = *(uint32_t*)&pm;
                g_v64b[o] = *(uint32_t*)&pv;
            }
        }
    }
}

// ---------------- fused SpMM (CSR, pre-scaled bf16 payload, int4 eidx) -----------
// warp per node; lane holds cols (2*lane, 2*lane+1). Pure payload sums;
// src-side weights applied once at the end.
__global__ __launch_bounds__(256) void spmm_fused_kernel(
    const float* __restrict__ sample, float* __restrict__ out, int n)
{
    int s    = (blockIdx.x * 256 + threadIdx.x) >> 5;
    int lane = threadIdx.x & 31;
    if (s >= n) return;

    float2 ws = g_w2[s];
    int start = g_rowstart[s];   // multiple of 8
    int cnt   = g_ecnt[s];

    // self-loop: payload already includes dst factor; src factor applied at end
    float2 msl = __bfloat1622float2(*(__nv_bfloat162*)&g_m64b[(size_t)s * 32 + lane]);
    float2 vsl = __bfloat1622float2(*(__nv_bfloat162*)&g_v64b[(size_t)s * 32 + lane]);
    float am0 = msl.x, am1 = msl.y;
    float av0 = vsl.x, av1 = vsl.y;

    const int4* ep = (const int4*)(g_eidx + start);
    int j = 0;
    for (; j + 8 <= cnt; j += 8) {
        int4 e0 = ep[(j >> 2)];
        int4 e1 = ep[(j >> 2) + 1];
        int d[8] = {e0.x, e0.y, e0.z, e0.w, e1.x, e1.y, e1.z, e1.w};
        uint32_t mu[8], vu[8];
        #pragma unroll
        for (int q = 0; q < 8; q++) mu[q] = g_m64b[(size_t)d[q] * 32 + lane];
        #pragma unroll
        for (int q = 0; q < 8; q++) vu[q] = g_v64b[(size_t)d[q] * 32 + lane];
        #pragma unroll
        for (int q = 0; q < 8; q++) {
            float2 mm = __bfloat1622float2(*(__nv_bfloat162*)&mu[q]);
            float2 vv = __bfloat1622float2(*(__nv_bfloat162*)&vu[q]);
            am0 += mm.x; am1 += mm.y;
            av0 += vv.x; av1 += vv.y;
        }
    }
    for (; j < cnt; j++) {
        int d = g_eidx[start + j];
        uint32_t mu = g_m64b[(size_t)d * 32 + lane];
        uint32_t vu = g_v64b[(size_t)d * 32 + lane];
        float2 mm = __bfloat1622float2(*(__nv_bfloat162*)&mu);
        float2 vv = __bfloat1622float2(*(__nv_bfloat162*)&vu);
        am0 += mm.x; am1 += mm.y;
        av0 += vv.x; av1 += vv.y;
    }

    // apply src-side weights once; finalize + log_softmax
    float mean0 = ws.x * am0, mean1 = ws.x * am1;
    float var0  = ws.y * av0, var1  = ws.y * av1;
    size_t base = (size_t)s * CLS;
    float2 sp = *(const float2*)(sample + base + lane * 2);
    float va = mean0 + sp.x * sqrtf(fmaxf(var0, 0.f));
    float vb = mean1 + sp.y * sqrtf(fmaxf(var1, 0.f));
    float mx = fmaxf(va, vb);
    #pragma unroll
    for (int o = 16; o; o >>= 1) mx = fmaxf(mx, __shfl_xor_sync(0xFFFFFFFFu, mx, o));
    float sum = expf(va - mx) + expf(vb - mx);
    #pragma unroll
    for (int o = 16; o; o >>= 1) sum += __shfl_xor_sync(0xFFFFFFFFu, sum, o);
    float lse = mx + logf(sum);
    *(float2*)(out + base + lane * 2) = make_float2(va - lse, vb - lse);
}

// ---------------- launch ----------------
extern "C" void kernel_launch(void* const* d_in, const int* in_sizes, int n_in,
                              void* d_out, int out_size)
{
    const float* x      = (const float*)d_in[0];
    const float* Wm0    = (const float*)d_in[1];
    const float* bm0    = (const float*)d_in[2];
    const float* Wv0    = (const float*)d_in[3];
    const float* bv0    = (const float*)d_in[4];
    const float* Wm1    = (const float*)d_in[5];
    const float* bm1    = (const float*)d_in[6];
    const float* Wv1    = (const float*)d_in[7];
    const float* bv1    = (const float*)d_in[8];
    const float* sample = (const float*)d_in[9];
    const int*   esrc   = (const int*)d_in[10];
    const int*   edst   = (const int*)d_in[11];
    float* out = (float*)d_out;

    int M = in_sizes[0] / FIN;     // 100000
    int E = in_sizes[10];          // 3200000
    if (M > NNODE) M = NNODE;
    if (E > MAXE - 7 * NNODE) E = MAXE - 7 * NNODE;   // padded CSR must fit
    int nblk = (M + 1023) / 1024;

    static cudaStream_t sB = nullptr;
    static cudaEvent_t evF = nullptr, evW = nullptr, evB = nullptr;
    if (sB == nullptr) {
        cudaStreamCreateWithFlags(&sB, cudaStreamNonBlocking);
        cudaEventCreateWithFlags(&evF, cudaEventDisableTiming);
        cudaEventCreateWithFlags(&evW, cudaEventDisableTiming);
        cudaEventCreateWithFlags(&evB, cudaEventDisableTiming);
    }

    cudaFuncSetAttribute(gemm0_mma_kernel, cudaFuncAttributeMaxDynamicSharedMemorySize, G0_SMEM);
    cudaFuncSetAttribute(layer1_mma_kernel, cudaFuncAttributeMaxDynamicSharedMemorySize, L1_SMEM);

    // fork: CSR build + degree weights on sB, dense pipeline on default stream
    cudaEventRecord(evF, 0);
    cudaStreamWaitEvent(sB, evF, 0);

    zero_ecnt_kernel    <<<(M + 255) / 256, 256, 0, sB>>>(M);
    count_edges_kernel  <<<(E + 255) / 256, 256, 0, sB>>>(esrc, E);
    scan_blocks_kernel  <<<nblk, 1024, 0, sB>>>(M);
    scan_tops_kernel    <<<1, 128, 0, sB>>>(nblk);
    scan_add_deg_kernel <<<(M + 255) / 256, 256, 0, sB>>>(M);
    cudaEventRecord(evW, sB);                          // w2 + rowstart ready
    scatter_edges_kernel<<<(E + 255) / 256, 256, 0, sB>>>(esrc, edst, E);
    cudaEventRecord(evB, sB);                          // full CSR ready

    // dense pipeline; layer1 epilogue consumes g_w2 -> join evW first
    dim3 g0(4, (M + 127) / 128);
    gemm0_mma_kernel<<<g0, 256, G0_SMEM>>>(x, Wm0, bm0, Wv0, bv0, M);
    cudaStreamWaitEvent(0, evW, 0);
    layer1_mma_kernel<<<(M + 127) / 128, 256, L1_SMEM>>>(Wm1, bm1, Wv1, bv1, M);

    // join: spmm needs scattered edges + layer1 output
    cudaStreamWaitEvent(0, evB, 0);
    spmm_fused_kernel<<<((size_t)M * 32 + 255) / 256, 256>>>(sample, out, M);
}

// round 17
// speedup vs baseline: 1.6589x; 1.0026x over previous
#include <cuda_runtime.h>
#include <cuda_bf16.h>
#include <math.h>
#include <stdint.h>

#define NNODE 100000
#define MAXE  4000000
#define FIN   512
#define HID   256
#define CLS   64

// ---------------- scratch (static device globals; no allocation) ----------------
__device__ float    g_Hm[(size_t)NNODE * HID];   // elu(x@Wm0+bm0)
__device__ float    g_Hv[(size_t)NNODE * HID];   // relu(x@Wv0+bv0)
__device__ uint32_t g_m64b[(size_t)NNODE * 32];  // dis[d]*mean*attn, bf16x2 packed
__device__ uint32_t g_v64b[(size_t)NNODE * 32];  // di[d]*var*attn^2, bf16x2 packed
__device__ int      g_ecnt[NNODE];               // out-degree (no self loop)
__device__ int      g_rowstart[NNODE];           // CSR row starts (8-padded)
__device__ int      g_fill[NNODE];               // scatter cursors
__device__ int      g_bsums[128];                // scan block sums
__device__ int      g_eidx[MAXE];                // CSR dst indices
__device__ float2   g_w2[NNODE];                 // (deg^-0.5, deg^-1)
__device__ float    g_Wt0[2][(size_t)HID * FIN]; // layer-0 weights [n][k]
__device__ float    g_Wt1[2][(size_t)CLS * HID]; // layer-1 weights [n][k]

// ---------------- weight transpose (runs on side stream, hidden) ----------------
__global__ void transpose_w_kernel(const float* __restrict__ Wm0, const float* __restrict__ Wv0,
                                   const float* __restrict__ Wm1, const float* __restrict__ Wv1) {
    int i = blockIdx.x * 256 + threadIdx.x;
    if (i < FIN * HID) {
        int k = i / HID, n = i % HID;
        g_Wt0[0][(size_t)n * FIN + k] = Wm0[i];
        g_Wt0[1][(size_t)n * FIN + k] = Wv0[i];
    }
    if (i < HID * CLS) {
        int k = i / CLS, n = i % CLS;
        g_Wt1[0][n * HID + k] = Wm1[i];
        g_Wt1[1][n * HID + k] = Wv1[i];
    }
}

// ---------------- degree + CSR build ----------------
__global__ void zero_ecnt_kernel(int n) {
    int i = blockIdx.x * blockDim.x + threadIdx.x;
    if (i < n) g_ecnt[i] = 0;
}
__global__ void count_edges_kernel(const int* __restrict__ src, int e) {
    int i = blockIdx.x * blockDim.x + threadIdx.x;
    if (i < e) atomicAdd(&g_ecnt[src[i]], 1);
}
// scan over 8-PADDED counts so every row start is 8-aligned (32B) for int4 loads
__global__ __launch_bounds__(1024) void scan_blocks_kernel(int n) {
    __shared__ int sh[1024];
    int tid = threadIdx.x;
    int gid = blockIdx.x * 1024 + tid;
    int v = (gid < n) ? ((g_ecnt[gid] + 7) & ~7) : 0;
    sh[tid] = v;
    __syncthreads();
    for (int off = 1; off < 1024; off <<= 1) {
        int t = (tid >= off) ? sh[tid - off] : 0;
        __syncthreads();
        sh[tid] += t;
        __syncthreads();
    }
    if (gid < n) g_rowstart[gid] = sh[tid] - v;   // exclusive
    if (tid == 1023) g_bsums[blockIdx.x] = sh[1023];
}
__global__ void scan_tops_kernel(int nblk) {
    __shared__ int sh[128];
    int tid = threadIdx.x;
    int v = (tid < nblk) ? g_bsums[tid] : 0;
    sh[tid] = v;
    __syncthreads();
    for (int off = 1; off < 128; off <<= 1) {
        int t = (tid >= off) ? sh[tid - off] : 0;
        __syncthreads();
        sh[tid] += t;
        __syncthreads();
    }
    if (tid < nblk) g_bsums[tid] = sh[tid] - v;   // exclusive
}
__global__ void scan_add_deg_kernel(int n) {
    int i = blockIdx.x * blockDim.x + threadIdx.x;
    if (i < n) {
        int rs = g_rowstart[i] + g_bsums[i >> 10];
        g_rowstart[i] = rs;
        g_fill[i] = rs;
        float c = (float)(g_ecnt[i] + 1);   // + self loop
        g_w2[i] = make_float2(1.0f / sqrtf(c), 1.0f / c);
    }
}
__global__ void scatter_edges_kernel(const int* __restrict__ src,
                                     const int* __restrict__ dst, int e) {
    int i = blockIdx.x * blockDim.x + threadIdx.x;
    if (i < e) {
        int pos = atomicAdd(&g_fill[src[i]], 1);
        g_eidx[pos] = dst[i];
    }
}

// ---------------- mma.sync + cp.async + ldmatrix helpers ------------------------
__device__ __forceinline__ void mma_tf32(float* c, const uint32_t* a, const uint32_t* b) {
    asm volatile(
        "mma.sync.aligned.m16n8k8.row.col.f32.tf32.tf32.f32 "
        "{%0,%1,%2,%3}, {%4,%5,%6,%7}, {%8,%9}, {%0,%1,%2,%3};"
        : "+f"(c[0]), "+f"(c[1]), "+f"(c[2]), "+f"(c[3])
        : "r"(a[0]), "r"(a[1]), "r"(a[2]), "r"(a[3]), "r"(b[0]), "r"(b[1]));
}
__device__ __forceinline__ void ldsm_x4(uint32_t* r, uint32_t addr) {
    asm volatile("ldmatrix.sync.aligned.m8n8.x4.shared.b16 {%0,%1,%2,%3}, [%4];"
                 : "=r"(r[0]), "=r"(r[1]), "=r"(r[2]), "=r"(r[3]) : "r"(addr));
}
__device__ __forceinline__ void ldsm_x2(uint32_t* r, uint32_t addr) {
    asm volatile("ldmatrix.sync.aligned.m8n8.x2.shared.b16 {%0,%1}, [%2];"
                 : "=r"(r[0]), "=r"(r[1]) : "r"(addr));
}
__device__ __forceinline__ uint32_t smem_u32(const void* p) {
    uint32_t a;
    asm("{ .reg .u64 t; cvta.to.shared.u64 t, %1; cvt.u32.u64 %0, t; }" : "=r"(a) : "l"(p));
    return a;
}
__device__ __forceinline__ void cp_async16(uint32_t dst, const void* src, int srcsize) {
    asm volatile("cp.async.cg.shared.global [%0], [%1], 16, %2;"
                 :: "r"(dst), "l"(src), "r"(srcsize) : "memory");
}
__device__ __forceinline__ void cp_commit() {
    asm volatile("cp.async.commit_group;" ::: "memory");
}
__device__ __forceinline__ void cp_wait1() {
    asm volatile("cp.async.wait_group 1;" ::: "memory");
}
__device__ __forceinline__ void cp_wait0() {
    asm volatile("cp.async.wait_group 0;" ::: "memory");
}

// ---------------- layer-0 GEMM: H = act(X @ W + b), cp.async + ldmatrix ----------
// BM=128, BN=128, BK=16. A smem [m][k] stride 20; B smem [n][k] stride 20.
// Row stride 20 floats => ldmatrix 8-row phases hit all 32 banks once (no conflict).
#define G0_STAGE (128 * 20 + 128 * 20)            // 5120 floats
#define G0_SMEM  (3 * G0_STAGE * 4)               // 61440 bytes

__global__ __launch_bounds__(256, 2) void gemm0_mma_kernel(
    const float* __restrict__ X,
    const float* __restrict__ bm, const float* __restrict__ bv,
    int M)
{
    extern __shared__ float smem[];
    uint32_t smemB = smem_u32(smem);

    int nb   = blockIdx.x & 1;
    int path = blockIdx.x >> 1;
    const float* Wt   = g_Wt0[path];               // [n][k]
    const float* bias = path ? bv : bm;
    float* H          = path ? g_Hv : g_Hm;

    int rowBase = blockIdx.y * 128;
    int t = threadIdx.x, wid = t >> 5, lane = t & 31;
    int warpM = wid >> 2, warpN = wid & 3;
    int lr = lane >> 2, lc = lane & 3;

    // cp.async coords: 512 16B-chunks each for A and B; 2 per thread each
    int rA0 = t >> 2,          kq = t & 3;
    int rA1 = (t + 256) >> 2;
    int szA0 = (rowBase + rA0 < M) ? 16 : 0;
    int szA1 = (rowBase + rA1 < M) ? 16 : 0;
    const float* XA0 = X + (size_t)(rowBase + rA0) * FIN + kq * 4;
    const float* XA1 = X + (size_t)(rowBase + rA1) * FIN + kq * 4;
    const float* WB0 = Wt + (size_t)(nb * 128 + rA0) * FIN + kq * 4;
    const float* WB1 = Wt + (size_t)(nb * 128 + rA1) * FIN + kq * 4;
    uint32_t dA0 = smemB + (rA0 * 20 + kq * 4) * 4;
    uint32_t dA1 = smemB + (rA1 * 20 + kq * 4) * 4;
    uint32_t dB0 = smemB + (128 * 20 + rA0 * 20 + kq * 4) * 4;
    uint32_t dB1 = smemB + (128 * 20 + rA1 * 20 + kq * 4) * 4;

    // ldmatrix lane address components (bytes)
    uint32_t laneA = ((lane & 15) * 20 + (lane >> 4) * 4) * 4;
    uint32_t laneB = ((lane & 7) * 20 + ((lane >> 3) & 1) * 4) * 4;

    float acc[4][4][4];
    #pragma unroll
    for (int i = 0; i < 4; i++)
        #pragma unroll
        for (int j = 0; j < 4; j++)
            #pragma unroll
            for (int q = 0; q < 4; q++) acc[i][j][q] = 0.0f;

    #pragma unroll
    for (int pc = 0; pc < 2; pc++) {
        uint32_t so = pc * G0_STAGE * 4;
        cp_async16(dA0 + so, XA0 + pc * 16, szA0);
        cp_async16(dA1 + so, XA1 + pc * 16, szA1);
        cp_async16(dB0 + so, WB0 + pc * 16, 16);
        cp_async16(dB1 + so, WB1 + pc * 16, 16);
        cp_commit();
    }

    for (int c = 0; c < 32; c++) {
        if (c < 30) cp_wait1(); else cp_wait0();
        __syncthreads();

        int cur = c - (c / 3) * 3;   // c % 3
        uint32_t sAb = smemB + cur * G0_STAGE * 4;
        uint32_t sBb = sAb + 128 * 20 * 4;

        #pragma unroll
        for (int ks = 0; ks < 2; ks++) {
            uint32_t ko = ks * 32;   // 8 floats
            uint32_t afr[4][4];
            #pragma unroll
            for (int mt = 0; mt < 4; mt++)
                ldsm_x4(afr[mt], sAb + laneA + (uint32_t)((warpM * 64 + mt * 16) * 80) + ko);
            #pragma unroll
            for (int nt = 0; nt < 4; nt++) {
                uint32_t bfr[2];
                ldsm_x2(bfr, sBb + laneB + (uint32_t)((warpN * 32 + nt * 8) * 80) + ko);
                #pragma unroll
                for (int mt = 0; mt < 4; mt++) mma_tf32(acc[mt][nt], afr[mt], bfr);
            }
        }

        if (c + 2 < 32) {
            int cn = c + 2;
            int s  = cn - (cn / 3) * 3;
            uint32_t so = s * G0_STAGE * 4;
            cp_async16(dA0 + so, XA0 + cn * 16, szA0);
            cp_async16(dA1 + so, XA1 + cn * 16, szA1);
            cp_async16(dB0 + so, WB0 + cn * 16, 16);
            cp_async16(dB1 + so, WB1 + cn * 16, 16);
            cp_commit();
        }
    }

    // epilogue: bias + activation, fp32 store
    #pragma unroll
    for (int mt = 0; mt < 4; mt++) {
        int r0 = rowBase + warpM * 64 + mt * 16 + lr;
        #pragma unroll
        for (int nt = 0; nt < 4; nt++) {
            int cb = nb * 128 + warpN * 32 + nt * 8 + lc * 2;
            float b0 = bias[cb], b1 = bias[cb + 1];
            #pragma unroll
            for (int half = 0; half < 2; half++) {
                int r = r0 + half * 8;
                if (r >= M) continue;
                float v0 = acc[mt][nt][half * 2 + 0] + b0;
                float v1 = acc[mt][nt][half * 2 + 1] + b1;
                if (path == 0) {
                    v0 = (v0 > 0.0f) ? v0 : expm1f(v0);
                    v1 = (v1 > 0.0f) ? v1 : expm1f(v1);
                } else {
                    v0 = fmaxf(v0, 0.0f);
                    v1 = fmaxf(v1, 0.0f);
                }
                *(float2*)(H + (size_t)r * HID + cb) = make_float2(v0, v1);
            }
        }
    }
}

// ---------------- layer-1 via tf32 HMMA + ldmatrix, cp.async 3-stage -------------
// A smem [m][k] stride 20; B smem [n][k] stride 20 (from g_Wt1).
#define L1_STAGE (128 * 20 + 64 * 20)             // 3840 floats
#define L1_SMEM  (3 * L1_STAGE * 4)               // 46080 bytes

__global__ __launch_bounds__(256, 2) void layer1_mma_kernel(
    const float* __restrict__ bm1, const float* __restrict__ bv1, int M)
{
    extern __shared__ float smem[];
    uint32_t smemB = smem_u32(smem);

    int rowBase = blockIdx.x * 128;
    int t = threadIdx.x, wid = t >> 5, lane = t & 31;
    int warpM = wid >> 2, warpN = wid & 3;
    int lr = lane >> 2, lc = lane & 3;

    int rA0 = t >> 2,          kq = t & 3;
    int rA1 = (t + 256) >> 2;
    int szA0 = (rowBase + rA0 < M) ? 16 : 0;
    int szA1 = (rowBase + rA1 < M) ? 16 : 0;
    uint32_t dA0 = smemB + (rA0 * 20 + kq * 4) * 4;
    uint32_t dA1 = smemB + (rA1 * 20 + kq * 4) * 4;
    uint32_t dB  = smemB + (128 * 20 + rA0 * 20 + kq * 4) * 4;   // 256 chunks: rA0 = t>>2 in 0..63

    uint32_t laneA = ((lane & 15) * 20 + (lane >> 4) * 4) * 4;
    uint32_t laneB = ((lane & 7) * 20 + ((lane >> 3) & 1) * 4) * 4;

    float acc0[4][2][4], acc1[4][2][4];
    #pragma unroll
    for (int i = 0; i < 4; i++)
        #pragma unroll
        for (int j = 0; j < 2; j++)
            #pragma unroll
            for (int q = 0; q < 4; q++) { acc0[i][j][q] = 0.f; acc1[i][j][q] = 0.f; }

    #pragma unroll
    for (int p = 0; p < 2; p++) {
        const float* A  = p ? g_Hv : g_Hm;
        const float* Wt = g_Wt1[p];                // [64 n][256 k]
        const float* A0 = A + (size_t)(rowBase + rA0) * HID + kq * 4;
        const float* A1 = A + (size_t)(rowBase + rA1) * HID + kq * 4;
        const float* WB = Wt + (size_t)rA0 * HID + kq * 4;   // rows 0..63 (t<256)

        __syncthreads();

        #pragma unroll
        for (int pc = 0; pc < 2; pc++) {
            uint32_t so = pc * L1_STAGE * 4;
            cp_async16(dA0 + so, A0 + pc * 16, szA0);
            cp_async16(dA1 + so, A1 + pc * 16, szA1);
            cp_async16(dB + so, WB + pc * 16, 16);
            cp_commit();
        }

        for (int c = 0; c < 16; c++) {
            if (c < 14) cp_wait1(); else cp_wait0();
            __syncthreads();

            int cur = c - (c / 3) * 3;
            uint32_t sAb = smemB + cur * L1_STAGE * 4;
            uint32_t sBb = sAb + 128 * 20 * 4;

            #pragma unroll
            for (int ks = 0; ks < 2; ks++) {
                uint32_t ko = ks * 32;
                uint32_t afr[4][4];
                #pragma unroll
                for (int mt = 0; mt < 4; mt++)
                    ldsm_x4(afr[mt], sAb + laneA + (uint32_t)((warpM * 64 + mt * 16) * 80) + ko);
                #pragma unroll
                for (int nt = 0; nt < 2; nt++) {
                    uint32_t bfr[2];
                    ldsm_x2(bfr, sBb + laneB + (uint32_t)((warpN * 16 + nt * 8) * 80) + ko);
                    #pragma unroll
                    for (int mt = 0; mt < 4; mt++)
                        mma_tf32(p ? acc1[mt][nt] : acc0[mt][nt], afr[mt], bfr);
                }
            }

            if (c + 2 < 16) {
                int cn = c + 2;
                int s  = cn - (cn / 3) * 3;
                uint32_t so = s * L1_STAGE * 4;
                cp_async16(dA0 + so, A0 + cn * 16, szA0);
                cp_async16(dA1 + so, A1 + cn * 16, szA1);
                cp_async16(dB + so, WB + cn * 16, 16);
                cp_commit();
            }
        }
    }

    // fused epilogue: elu/relu + attn coupling + dst-degree pre-scale, bf16x2 pack
    #pragma unroll
    for (int mt = 0; mt < 4; mt++) {
        int r0 = rowBase + warpM * 64 + mt * 16 + lr;
        #pragma unroll
        for (int nt = 0; nt < 2; nt++) {
            int cb = warpN * 16 + nt * 8 + lc * 2;
            float bm0c = bm1[cb], bm1c = bm1[cb + 1];
            float bv0c = bv1[cb], bv1c = bv1[cb + 1];
            #pragma unroll
            for (int half = 0; half < 2; half++) {
                int r = r0 + half * 8;
                if (r >= M) continue;
                float2 wr = g_w2[r];   // (dis[r], di[r])
                float m0 = acc0[mt][nt][half * 2 + 0] + bm0c;
                float m1 = acc0[mt][nt][half * 2 + 1] + bm1c;
                m0 = (m0 > 0.0f) ? m0 : expm1f(m0);
                m1 = (m1 > 0.0f) ? m1 : expm1f(m1);
                float v0 = fmaxf(acc1[mt][nt][half * 2 + 0] + bv0c, 0.0f) + 1e-6f;
                float v1 = fmaxf(acc1[mt][nt][half * 2 + 1] + bv1c, 0.0f) + 1e-6f;
                float a0 = expf(-v0), a1 = expf(-v1);
                __nv_bfloat162 pm = __float22bfloat162_rn(
                    make_float2(wr.x * m0 * a0, wr.x * m1 * a1));
                __nv_bfloat162 pv = __float22bfloat162_rn(
                    make_float2(wr.y * v0 * a0 * a0, wr.y * v1 * a1 * a1));
                size_t o = (size_t)r * 32 + (cb >> 1);
                g_m64b[o] = *(uint32_t*)&pm;
                g_v64b[o] = *(uint32_t*)&pv;
            }
        }
    }
}

// ---------------- fused SpMM (CSR, pre-scaled bf16 payload, int4 eidx) -----------
__global__ __launch_bounds__(256) void spmm_fused_kernel(
    const float* __restrict__ sample, float* __restrict__ out, int n)
{
    int s    = (blockIdx.x * 256 + threadIdx.x) >> 5;
    int lane = threadIdx.x & 31;
    if (s >= n) return;

    float2 ws = g_w2[s];
    int start = g_rowstart[s];   // multiple of 8
    int cnt   = g_ecnt[s];

    float2 msl = __bfloat1622float2(*(__nv_bfloat162*)&g_m64b[(size_t)s * 32 + lane]);
    float2 vsl = __bfloat1622float2(*(__nv_bfloat162*)&g_v64b[(size_t)s * 32 + lane]);
    float am0 = msl.x, am1 = msl.y;
    float av0 = vsl.x, av1 = vsl.y;

    const int4* ep = (const int4*)(g_eidx + start);
    int j = 0;
    for (; j + 8 <= cnt; j += 8) {
        int4 e0 = ep[(j >> 2)];
        int4 e1 = ep[(j >> 2) + 1];
        int d[8] = {e0.x, e0.y, e0.z, e0.w, e1.x, e1.y, e1.z, e1.w};
        uint32_t mu[8], vu[8];
        #pragma unroll
        for (int q = 0; q < 8; q++) mu[q] = g_m64b[(size_t)d[q] * 32 + lane];
        #pragma unroll
        for (int q = 0; q < 8; q++) vu[q] = g_v64b[(size_t)d[q] * 32 + lane];
        #pragma unroll
        for (int q = 0; q < 8; q++) {
            float2 mm = __bfloat1622float2(*(__nv_bfloat162*)&mu[q]);
            float2 vv = __bfloat1622float2(*(__nv_bfloat162*)&vu[q]);
            am0 += mm.x; am1 += mm.y;
            av0 += vv.x; av1 += vv.y;
        }
    }
    for (; j < cnt; j++) {
        int d = g_eidx[start + j];
        uint32_t mu = g_m64b[(size_t)d * 32 + lane];
        uint32_t vu = g_v64b[(size_t)d * 32 + lane];
        float2 mm = __bfloat1622float2(*(__nv_bfloat162*)&mu);
        float2 vv = __bfloat1622float2(*(__nv_bfloat162*)&vu);
        am0 += mm.x; am1 += mm.y;
        av0 += vv.x; av1 += vv.y;
    }

    float mean0 = ws.x * am0, mean1 = ws.x * am1;
    float var0  = ws.y * av0, var1  = ws.y * av1;
    size_t base = (size_t)s * CLS;
    float2 sp = *(const float2*)(sample + base + lane * 2);
    float va = mean0 + sp.x * sqrtf(fmaxf(var0, 0.f));
    float vb = mean1 + sp.y * sqrtf(fmaxf(var1, 0.f));
    float mx = fmaxf(va, vb);
    #pragma unroll
    for (int o = 16; o; o >>= 1) mx = fmaxf(mx, __shfl_xor_sync(0xFFFFFFFFu, mx, o));
    float sum = expf(va - mx) + expf(vb - mx);
    #pragma unroll
    for (int o = 16; o; o >>= 1) sum += __shfl_xor_sync(0xFFFFFFFFu, sum, o);
    float lse = mx + logf(sum);
    *(float2*)(out + base + lane * 2) = make_float2(va - lse, vb - lse);
}

// ---------------- launch ----------------
extern "C" void kernel_launch(void* const* d_in, const int* in_sizes, int n_in,
                              void* d_out, int out_size)
{
    const float* x      = (const float*)d_in[0];
    const float* Wm0    = (const float*)d_in[1];
    const float* bm0    = (const float*)d_in[2];
    const float* Wv0    = (const float*)d_in[3];
    const float* bv0    = (const float*)d_in[4];
    const float* Wm1    = (const float*)d_in[5];
    const float* bm1    = (const float*)d_in[6];
    const float* Wv1    = (const float*)d_in[7];
    const float* bv1    = (const float*)d_in[8];
    const float* sample = (const float*)d_in[9];
    const int*   esrc   = (const int*)d_in[10];
    const int*   edst   = (const int*)d_in[11];
    float* out = (float*)d_out;

    int M = in_sizes[0] / FIN;     // 100000
    int E = in_sizes[10];          // 3200000
    if (M > NNODE) M = NNODE;
    if (E > MAXE - 7 * NNODE) E = MAXE - 7 * NNODE;   // padded CSR must fit
    int nblk = (M + 1023) / 1024;

    static cudaStream_t sB = nullptr;
    static cudaEvent_t evF = nullptr, evT = nullptr, evW = nullptr, evB = nullptr;
    if (sB == nullptr) {
        cudaStreamCreateWithFlags(&sB, cudaStreamNonBlocking);
        cudaEventCreateWithFlags(&evF, cudaEventDisableTiming);
        cudaEventCreateWithFlags(&evT, cudaEventDisableTiming);
        cudaEventCreateWithFlags(&evW, cudaEventDisableTiming);
        cudaEventCreateWithFlags(&evB, cudaEventDisableTiming);
    }

    cudaFuncSetAttribute(gemm0_mma_kernel, cudaFuncAttributeMaxDynamicSharedMemorySize, G0_SMEM);
    cudaFuncSetAttribute(layer1_mma_kernel, cudaFuncAttributeMaxDynamicSharedMemorySize, L1_SMEM);

    // fork: transpose + CSR build on sB, dense pipeline on default stream
    cudaEventRecord(evF, 0);
    cudaStreamWaitEvent(sB, evF, 0);

    transpose_w_kernel  <<<(FIN * HID + 255) / 256, 256, 0, sB>>>(Wm0, Wv0, Wm1, Wv1);
    cudaEventRecord(evT, sB);                          // transposed weights ready
    zero_ecnt_kernel    <<<(M + 255) / 256, 256, 0, sB>>>(M);
    count_edges_kernel  <<<(E + 255) / 256, 256, 0, sB>>>(esrc, E);
    scan_blocks_kernel  <<<nblk, 1024, 0, sB>>>(M);
    scan_tops_kernel    <<<1, 128, 0, sB>>>(nblk);
    scan_add_deg_kernel <<<(M + 255) / 256, 256, 0, sB>>>(M);
    cudaEventRecord(evW, sB);                          // w2 + rowstart ready
    scatter_edges_kernel<<<(E + 255) / 256, 256, 0, sB>>>(esrc, edst, E);
    cudaEventRecord(evB, sB);                          // full CSR ready

    // dense pipeline
    cudaStreamWaitEvent(0, evT, 0);
    dim3 g0(4, (M + 127) / 128);
    gemm0_mma_kernel<<<g0, 256, G0_SMEM>>>(x, bm0, bv0, M);
    cudaStreamWaitEvent(0, evW, 0);
    layer1_mma_kernel<<<(M + 127) / 128, 256, L1_SMEM>>>(bm1, bv1, M);

    // join: spmm needs scattered edges + layer1 output
    cudaStreamWaitEvent(0, evB, 0);
    spmm_fused_kernel<<<((size_t)M * 32 + 255) / 256, 256>>>(sample, out, M);
}